// round 2
// baseline (speedup 1.0000x reference)
#include <cuda_runtime.h>
#include <cuda_bf16.h>
#include <cstdint>

#define NN 50000
#define EE 1600000
#define IN_DIM 1000
#define HID 256
#define OUTD 2

// ---------------- scratch (device globals; no allocation allowed) ----------
__device__ float g_deg[NN];               // degree, then dinv in place
__device__ float g_h[(size_t)NN * HID];   // X @ W1
__device__ float g_a[(size_t)NN * HID];   // aggregated -> relu activations
__device__ float g_z[(size_t)NN * OUTD];  // a @ W2
__device__ int   g_shift;                 // 0: edge_index is int32, 1: int64

// ---------------- helpers ---------------------------------------------------
__device__ __forceinline__ void red_add_v4(float* p, float a, float b, float c, float d) {
    asm volatile("red.global.add.v4.f32 [%0], {%1,%2,%3,%4};"
                 :: "l"(p), "f"(a), "f"(b), "f"(c), "f"(d) : "memory");
}
__device__ __forceinline__ void red_add_v2(float* p, float a, float b) {
    asm volatile("red.global.add.v2.f32 [%0], {%1,%2};"
                 :: "l"(p), "f"(a), "f"(b) : "memory");
}

// ---------------- edge dtype detection ---------------------------------------
// If edge_index is int64 (values < 50000), every odd 32-bit word of the buffer
// head is 0. If int32, odd words are random edge ids. One warp samples 2048
// odd words; all-zero => int64 (shift=1), else int32 (shift=0).
__global__ void k_detect(const int* __restrict__ ei32) {
    int lane = threadIdx.x;
    unsigned any = 0;
    for (int base = 0; base < 2048; base += 32) {
        int v = ei32[2 * (base + lane) + 1];
        any |= __ballot_sync(0xffffffffu, v != 0);
    }
    if (lane == 0) g_shift = (any == 0) ? 1 : 0;
}

__device__ __forceinline__ int edge_src(const int* ei, int e, int sh) {
    return ei[(size_t)e << sh];
}
__device__ __forceinline__ int edge_dst(const int* ei, int e, int sh) {
    return ei[(size_t)(EE + e) << sh];
}

// ---------------- degree / dinv ---------------------------------------------
__global__ void k_deg_init() {
    int i = blockIdx.x * blockDim.x + threadIdx.x;
    if (i < NN) g_deg[i] = 1.0f;   // self-loop
}
__global__ void k_deg_acc(const int* __restrict__ ei) {
    int e = blockIdx.x * blockDim.x + threadIdx.x;
    if (e < EE) {
        int sh = g_shift;
        atomicAdd(&g_deg[edge_dst(ei, e, sh)], 1.0f);
    }
}
__global__ void k_dinv() {
    int i = blockIdx.x * blockDim.x + threadIdx.x;
    if (i < NN) {
        float dg = g_deg[i];
        g_deg[i] = (dg > 0.f) ? rsqrtf(dg) : 0.f;
    }
}

// ---------------- SGEMM 128x128x8, fp32, 8x8 register tile -------------------
// C[M,N] = A[M,K] @ B[K,N];  N multiple of 128, K multiple of 8, M ragged.
__global__ __launch_bounds__(256, 1)
void k_sgemm(const float* __restrict__ A, const float* __restrict__ B,
             float* __restrict__ C, int M, int Nn, int K) {
    __shared__ float As[8][128];
    __shared__ float Bs[8][128];
    const int tid = threadIdx.x;
    const int bm = blockIdx.x * 128;
    const int bn = blockIdx.y * 128;

    const int aRow = tid >> 1;          // 0..127
    const int aCol = (tid & 1) * 4;     // 0 or 4
    const int bRow = tid >> 5;          // 0..7
    const int bCol = (tid & 31) * 4;    // 0..124

    const int ty = tid >> 4;            // 0..15
    const int tx = tid & 15;            // 0..15

    float acc[8][8];
#pragma unroll
    for (int i = 0; i < 8; i++)
#pragma unroll
        for (int j = 0; j < 8; j++) acc[i][j] = 0.f;

    for (int k0 = 0; k0 < K; k0 += 8) {
        int gr = bm + aRow;
        float4 av;
        if (gr < M) av = *reinterpret_cast<const float4*>(A + (size_t)gr * K + k0 + aCol);
        else        av = make_float4(0.f, 0.f, 0.f, 0.f);
        As[aCol + 0][aRow] = av.x;
        As[aCol + 1][aRow] = av.y;
        As[aCol + 2][aRow] = av.z;
        As[aCol + 3][aRow] = av.w;
        float4 bv = *reinterpret_cast<const float4*>(B + (size_t)(k0 + bRow) * Nn + bn + bCol);
        *reinterpret_cast<float4*>(&Bs[bRow][bCol]) = bv;
        __syncthreads();

#pragma unroll
        for (int k = 0; k < 8; k++) {
            float ar[8], br[8];
#pragma unroll
            for (int i = 0; i < 8; i++) ar[i] = As[k][ty * 8 + i];
#pragma unroll
            for (int j = 0; j < 8; j++) br[j] = Bs[k][tx * 8 + j];
#pragma unroll
            for (int i = 0; i < 8; i++)
#pragma unroll
                for (int j = 0; j < 8; j++)
                    acc[i][j] = fmaf(ar[i], br[j], acc[i][j]);
        }
        __syncthreads();
    }

#pragma unroll
    for (int i = 0; i < 8; i++) {
        int r = bm + ty * 8 + i;
        if (r >= M) continue;
        float* crow = C + (size_t)r * Nn + bn + tx * 8;
#pragma unroll
        for (int j = 0; j < 8; j += 4)
            *reinterpret_cast<float4*>(crow + j) =
                make_float4(acc[i][j], acc[i][j+1], acc[i][j+2], acc[i][j+3]);
    }
}

// ---------------- layer-1 aggregation ----------------------------------------
// init with self-loop contribution: a[i,:] = dinv[i]^2 * h[i,:]
__global__ void k_self_init_hid() {
    int idx = blockIdx.x * blockDim.x + threadIdx.x;   // over NN*64 float4s
    if (idx >= NN * (HID / 4)) return;
    int node = idx >> 6;
    float dv = g_deg[node];
    float s = dv * dv;
    float4 v = reinterpret_cast<const float4*>(g_h)[idx];
    v.x *= s; v.y *= s; v.z *= s; v.w *= s;
    reinterpret_cast<float4*>(g_a)[idx] = v;
}

// one warp per edge: gather h[src]*norm, scatter-add into a[dst]
__global__ void k_edge_agg_hid(const int* __restrict__ ei) {
    int warp = (blockIdx.x * blockDim.x + threadIdx.x) >> 5;
    int lane = threadIdx.x & 31;
    if (warp >= EE) return;
    int sh = g_shift;
    int s = edge_src(ei, warp, sh);
    int d = edge_dst(ei, warp, sh);
    float nrm = g_deg[s] * g_deg[d];
    const float4* hrow = reinterpret_cast<const float4*>(g_h + (size_t)s * HID);
    float* orow = g_a + (size_t)d * HID;
#pragma unroll
    for (int it = 0; it < 2; it++) {
        int c = lane + it * 32;                 // float4 index 0..63
        float4 v = hrow[c];
        red_add_v4(orow + c * 4, v.x * nrm, v.y * nrm, v.z * nrm, v.w * nrm);
    }
}

// a = relu(a + b1)
__global__ void k_bias_relu(const float* __restrict__ b1) {
    int idx = blockIdx.x * blockDim.x + threadIdx.x;   // over NN*64 float4s
    if (idx >= NN * (HID / 4)) return;
    float4 v = reinterpret_cast<float4*>(g_a)[idx];
    float4 bb = reinterpret_cast<const float4*>(b1)[idx & 63];
    v.x = fmaxf(v.x + bb.x, 0.f);
    v.y = fmaxf(v.y + bb.y, 0.f);
    v.z = fmaxf(v.z + bb.z, 0.f);
    v.w = fmaxf(v.w + bb.w, 0.f);
    reinterpret_cast<float4*>(g_a)[idx] = v;
}

// ---------------- layer 2: z = a @ W2 (256 -> 2), warp per row ---------------
__global__ void k_gemm2(const float* __restrict__ W2) {
    int row = (blockIdx.x * blockDim.x + threadIdx.x) >> 5;
    int lane = threadIdx.x & 31;
    if (row >= NN) return;
    const float* ar = g_a + (size_t)row * HID;
    float acc0 = 0.f, acc1 = 0.f;
#pragma unroll
    for (int k = lane; k < HID; k += 32) {
        float v = ar[k];
        acc0 = fmaf(v, W2[k * 2 + 0], acc0);
        acc1 = fmaf(v, W2[k * 2 + 1], acc1);
    }
#pragma unroll
    for (int o = 16; o > 0; o >>= 1) {
        acc0 += __shfl_xor_sync(0xffffffffu, acc0, o);
        acc1 += __shfl_xor_sync(0xffffffffu, acc1, o);
    }
    if (lane == 0) {
        g_z[row * 2 + 0] = acc0;
        g_z[row * 2 + 1] = acc1;
    }
}

// out init with self-loop + bias: out[i,:] = dinv[i]^2 * z[i,:] + b2
__global__ void k_self_init_out(float* __restrict__ out, const float* __restrict__ b2) {
    int i = blockIdx.x * blockDim.x + threadIdx.x;
    if (i >= NN) return;
    float dv = g_deg[i];
    float s = dv * dv;
    out[i * 2 + 0] = s * g_z[i * 2 + 0] + b2[0];
    out[i * 2 + 1] = s * g_z[i * 2 + 1] + b2[1];
}

// per-edge scatter of 2 features
__global__ void k_edge_agg_out(const int* __restrict__ ei, float* __restrict__ out) {
    int e = blockIdx.x * blockDim.x + threadIdx.x;
    if (e >= EE) return;
    int sh = g_shift;
    int s = edge_src(ei, e, sh);
    int d = edge_dst(ei, e, sh);
    float nrm = g_deg[s] * g_deg[d];
    float2 v = reinterpret_cast<const float2*>(g_z)[s];
    red_add_v2(out + (size_t)d * 2, v.x * nrm, v.y * nrm);
}

// ---------------- launch -----------------------------------------------------
extern "C" void kernel_launch(void* const* d_in, const int* in_sizes, int n_in,
                              void* d_out, int out_size) {
    // robust input mapping by element count
    const float* x = nullptr;
    const float* W1 = nullptr;
    const float* b1 = nullptr;
    const float* W2 = nullptr;
    const float* b2 = nullptr;
    const int* ei = nullptr;
    for (int i = 0; i < n_in; i++) {
        switch (in_sizes[i]) {
            case NN * IN_DIM:      x  = (const float*)d_in[i]; break;      // 50,000,000
            case IN_DIM * HID:     W1 = (const float*)d_in[i]; break;      // 256,000
            case HID:              b1 = (const float*)d_in[i]; break;      // 256
            case HID * OUTD:       W2 = (const float*)d_in[i]; break;      // 512
            case OUTD:             b2 = (const float*)d_in[i]; break;      // 2
            case 2 * EE:           ei = (const int*)d_in[i]; break;        // 3,200,000
            default: break;
        }
    }
    float* out = (float*)d_out;

    float* d_h; cudaGetSymbolAddress((void**)&d_h, g_h);

    const int T = 256;
    // edge dtype detection + degree / dinv
    k_detect<<<1, 32>>>(ei);
    k_deg_init<<<(NN + T - 1) / T, T>>>();
    k_deg_acc<<<(EE + T - 1) / T, T>>>(ei);
    k_dinv<<<(NN + T - 1) / T, T>>>();

    // GEMM1: h = x @ W1
    {
        dim3 grid((NN + 127) / 128, HID / 128);
        k_sgemm<<<grid, 256>>>(x, W1, d_h, NN, HID, IN_DIM);
    }

    // aggregation 1
    k_self_init_hid<<<(NN * (HID / 4) + T - 1) / T, T>>>();
    {
        long long threads = (long long)EE * 32;
        k_edge_agg_hid<<<(unsigned)((threads + T - 1) / T), T>>>(ei);
    }
    k_bias_relu<<<(NN * (HID / 4) + T - 1) / T, T>>>(b1);

    // layer 2: transform first (A-hat commutes with per-node linear map)
    {
        long long threads = (long long)NN * 32;
        k_gemm2<<<(unsigned)((threads + T - 1) / T), T>>>(W2);
    }
    k_self_init_out<<<(NN + T - 1) / T, T>>>(out, b2);
    k_edge_agg_out<<<(EE + T - 1) / T, T>>>(ei, out);

    (void)out_size;
}

// round 3
// speedup vs baseline: 1.8064x; 1.8064x over previous
#include <cuda_runtime.h>
#include <cuda_bf16.h>
#include <cstdint>

#define NN 50000
#define EE 1600000
#define IN_DIM 1000
#define HID 256
#define OUTD 2

// ---------------- scratch (device globals; no allocation allowed) ----------
__device__ float g_deg[NN];               // degree, then dinv in place
__device__ float g_h[(size_t)NN * HID];   // X @ W1
__device__ float g_a[(size_t)NN * HID];   // aggregated activations
__device__ float g_z[(size_t)NN * OUTD];  // a @ W2
__device__ int   g_shift;                 // 0: edge_index int32, 1: int64

// ---------------- helpers ---------------------------------------------------
__device__ __forceinline__ void red_add_v4(float* p, float a, float b, float c, float d) {
    asm volatile("red.global.add.v4.f32 [%0], {%1,%2,%3,%4};"
                 :: "l"(p), "f"(a), "f"(b), "f"(c), "f"(d) : "memory");
}
__device__ __forceinline__ void red_add_v2(float* p, float a, float b) {
    asm volatile("red.global.add.v2.f32 [%0], {%1,%2};"
                 :: "l"(p), "f"(a), "f"(b) : "memory");
}
__device__ __forceinline__ uint32_t f2tf32(float f) {
    uint32_t u;
    asm("cvt.rna.tf32.f32 %0, %1;" : "=r"(u) : "f"(f));
    return u;
}

// ---------------- edge dtype detection ---------------------------------------
__global__ void k_detect(const int* __restrict__ ei32) {
    int lane = threadIdx.x;
    unsigned any = 0;
    for (int base = 0; base < 2048; base += 32) {
        int v = ei32[2 * (base + lane) + 1];
        any |= __ballot_sync(0xffffffffu, v != 0);
    }
    if (lane == 0) g_shift = (any == 0) ? 1 : 0;
}
__device__ __forceinline__ int edge_src(const int* ei, int e, int sh) {
    return ei[(size_t)e << sh];
}
__device__ __forceinline__ int edge_dst(const int* ei, int e, int sh) {
    return ei[(size_t)(EE + e) << sh];
}

// ---------------- degree / dinv ---------------------------------------------
__global__ void k_deg_init() {
    int i = blockIdx.x * blockDim.x + threadIdx.x;
    if (i < NN) g_deg[i] = 1.0f;   // self-loop
}
__global__ void k_deg_acc(const int* __restrict__ ei) {
    int e = blockIdx.x * blockDim.x + threadIdx.x;
    if (e < EE) {
        int sh = g_shift;
        atomicAdd(&g_deg[edge_dst(ei, e, sh)], 1.0f);
    }
}
__global__ void k_dinv() {
    int i = blockIdx.x * blockDim.x + threadIdx.x;
    if (i < NN) {
        float dg = g_deg[i];
        g_deg[i] = (dg > 0.f) ? rsqrtf(dg) : 0.f;
    }
}

// ---------------- GEMM1: tf32 mma.sync, 128x128x16 tile ----------------------
// C = A[M,K] @ B[K,N], M ragged, N=256, K=1000.
// Epilogue writes h = C and a = dinv[r]^2 * C (self-loop init fused).
#define BM 128
#define BN 128
#define BK 16
#define NIT ((IN_DIM + BK - 1) / BK)   // 63
#define AS_STRIDE 20                    // 16 + 4 pad (conflict-free frag reads)
#define BS_STRIDE 132                   // 128 + 4 pad

__global__ __launch_bounds__(256)
void k_mma_gemm(const float* __restrict__ A, const float* __restrict__ B,
                float* __restrict__ C, float* __restrict__ Cinit,
                const float* __restrict__ dinv) {
    __shared__ uint32_t As[2][BM * AS_STRIDE];
    __shared__ uint32_t Bs[2][BK * BS_STRIDE];

    const int tid = threadIdx.x;
    const int bm = blockIdx.x * BM;
    const int bn = blockIdx.y * BN;

    const int warp = tid >> 5;
    const int lane = tid & 31;
    const int g = lane >> 2;         // groupID 0..7
    const int t = lane & 3;          // threadID_in_group 0..3
    const int warpM = warp >> 1;     // 0..3  -> 32 rows each
    const int warpN = warp & 1;      // 0..1  -> 64 cols each

    // staging-load coordinates (fixed per thread)
    // A tile: 512 float4 (128 rows x 4 quads); thread handles idx = tid, tid+256
    // B tile: 512 float4 (16 k-rows x 32 quads)
    const int aRow0 = tid >> 2,          aQ0 = tid & 3;
    const int aRow1 = (tid + 256) >> 2,  aQ1 = (tid + 256) & 3;
    const int bK0 = tid >> 5,            bQ0 = tid & 31;
    const int bK1 = (tid + 256) >> 5,    bQ1 = (tid + 256) & 31;

    float acc[2][8][4];
#pragma unroll
    for (int mi = 0; mi < 2; mi++)
#pragma unroll
        for (int ni = 0; ni < 8; ni++)
#pragma unroll
            for (int c = 0; c < 4; c++) acc[mi][ni][c] = 0.f;

    float4 aStage[2], bStage[2];

    auto loadStage = [&](int k0) {
        const float4 z = make_float4(0.f, 0.f, 0.f, 0.f);
        int gr0 = bm + aRow0, gr1 = bm + aRow1;
        int ka0 = k0 + 4 * aQ0, ka1 = k0 + 4 * aQ1;
        aStage[0] = (gr0 < NN && ka0 < IN_DIM)
            ? *reinterpret_cast<const float4*>(A + (size_t)gr0 * IN_DIM + ka0) : z;
        aStage[1] = (gr1 < NN && ka1 < IN_DIM)
            ? *reinterpret_cast<const float4*>(A + (size_t)gr1 * IN_DIM + ka1) : z;
        int kb0 = k0 + bK0, kb1 = k0 + bK1;
        bStage[0] = (kb0 < IN_DIM)
            ? *reinterpret_cast<const float4*>(B + (size_t)kb0 * HID + bn + 4 * bQ0) : z;
        bStage[1] = (kb1 < IN_DIM)
            ? *reinterpret_cast<const float4*>(B + (size_t)kb1 * HID + bn + 4 * bQ1) : z;
    };

    auto storeStage = [&](int buf) {
        uint32_t* as = As[buf];
        uint32_t* bs = Bs[buf];
        as[aRow0 * AS_STRIDE + 4 * aQ0 + 0] = f2tf32(aStage[0].x);
        as[aRow0 * AS_STRIDE + 4 * aQ0 + 1] = f2tf32(aStage[0].y);
        as[aRow0 * AS_STRIDE + 4 * aQ0 + 2] = f2tf32(aStage[0].z);
        as[aRow0 * AS_STRIDE + 4 * aQ0 + 3] = f2tf32(aStage[0].w);
        as[aRow1 * AS_STRIDE + 4 * aQ1 + 0] = f2tf32(aStage[1].x);
        as[aRow1 * AS_STRIDE + 4 * aQ1 + 1] = f2tf32(aStage[1].y);
        as[aRow1 * AS_STRIDE + 4 * aQ1 + 2] = f2tf32(aStage[1].z);
        as[aRow1 * AS_STRIDE + 4 * aQ1 + 3] = f2tf32(aStage[1].w);
        bs[bK0 * BS_STRIDE + 4 * bQ0 + 0] = f2tf32(bStage[0].x);
        bs[bK0 * BS_STRIDE + 4 * bQ0 + 1] = f2tf32(bStage[0].y);
        bs[bK0 * BS_STRIDE + 4 * bQ0 + 2] = f2tf32(bStage[0].z);
        bs[bK0 * BS_STRIDE + 4 * bQ0 + 3] = f2tf32(bStage[0].w);
        bs[bK1 * BS_STRIDE + 4 * bQ1 + 0] = f2tf32(bStage[1].x);
        bs[bK1 * BS_STRIDE + 4 * bQ1 + 1] = f2tf32(bStage[1].y);
        bs[bK1 * BS_STRIDE + 4 * bQ1 + 2] = f2tf32(bStage[1].z);
        bs[bK1 * BS_STRIDE + 4 * bQ1 + 3] = f2tf32(bStage[1].w);
    };

    loadStage(0);
    storeStage(0);
    __syncthreads();

    int buf = 0;
    for (int it = 0; it < NIT; ++it) {
        if (it + 1 < NIT) loadStage((it + 1) * BK);

        const uint32_t* as = As[buf];
        const uint32_t* bs = Bs[buf];
#pragma unroll
        for (int k8 = 0; k8 < 2; k8++) {
            const int kk = k8 * 8;
            uint32_t afr[2][4];
#pragma unroll
            for (int mi = 0; mi < 2; mi++) {
                const int rb = warpM * 32 + mi * 16;
                afr[mi][0] = as[(rb + g    ) * AS_STRIDE + kk + t    ];
                afr[mi][1] = as[(rb + g + 8) * AS_STRIDE + kk + t    ];
                afr[mi][2] = as[(rb + g    ) * AS_STRIDE + kk + t + 4];
                afr[mi][3] = as[(rb + g + 8) * AS_STRIDE + kk + t + 4];
            }
            uint32_t bfr[8][2];
#pragma unroll
            for (int ni = 0; ni < 8; ni++) {
                const int n = warpN * 64 + ni * 8 + g;
                bfr[ni][0] = bs[(kk + t    ) * BS_STRIDE + n];
                bfr[ni][1] = bs[(kk + t + 4) * BS_STRIDE + n];
            }
#pragma unroll
            for (int mi = 0; mi < 2; mi++)
#pragma unroll
                for (int ni = 0; ni < 8; ni++) {
                    asm volatile(
                        "mma.sync.aligned.m16n8k8.row.col.f32.tf32.tf32.f32 "
                        "{%0,%1,%2,%3}, {%4,%5,%6,%7}, {%8,%9}, {%0,%1,%2,%3};"
                        : "+f"(acc[mi][ni][0]), "+f"(acc[mi][ni][1]),
                          "+f"(acc[mi][ni][2]), "+f"(acc[mi][ni][3])
                        : "r"(afr[mi][0]), "r"(afr[mi][1]),
                          "r"(afr[mi][2]), "r"(afr[mi][3]),
                          "r"(bfr[ni][0]), "r"(bfr[ni][1]));
                }
        }

        if (it + 1 < NIT) storeStage(buf ^ 1);
        __syncthreads();
        buf ^= 1;
    }

    // epilogue: write h and a = dinv^2 * h (self-loop init fused)
#pragma unroll
    for (int mi = 0; mi < 2; mi++) {
#pragma unroll
        for (int half = 0; half < 2; half++) {
            int r = bm + warpM * 32 + mi * 16 + g + half * 8;
            if (r >= NN) continue;
            float dv = dinv[r];
            float s = dv * dv;
            size_t rowOff = (size_t)r * HID + bn + warpN * 64 + 2 * t;
#pragma unroll
            for (int ni = 0; ni < 8; ni++) {
                float v0 = acc[mi][ni][half * 2 + 0];
                float v1 = acc[mi][ni][half * 2 + 1];
                *reinterpret_cast<float2*>(C + rowOff + ni * 8) = make_float2(v0, v1);
                *reinterpret_cast<float2*>(Cinit + rowOff + ni * 8) =
                    make_float2(s * v0, s * v1);
            }
        }
    }
}

// ---------------- layer-1 edge aggregation ------------------------------------
// one warp per edge: gather h[src]*norm, scatter-add into a[dst]
__global__ void k_edge_agg_hid(const int* __restrict__ ei) {
    int warp = (blockIdx.x * blockDim.x + threadIdx.x) >> 5;
    int lane = threadIdx.x & 31;
    if (warp >= EE) return;
    int sh = g_shift;
    int s = edge_src(ei, warp, sh);
    int d = edge_dst(ei, warp, sh);
    float nrm = g_deg[s] * g_deg[d];
    const float4* hrow = reinterpret_cast<const float4*>(g_h + (size_t)s * HID);
    float* orow = g_a + (size_t)d * HID;
#pragma unroll
    for (int it = 0; it < 2; it++) {
        int c = lane + it * 32;                 // float4 index 0..63
        float4 v = hrow[c];
        red_add_v4(orow + c * 4, v.x * nrm, v.y * nrm, v.z * nrm, v.w * nrm);
    }
}

// ---------------- layer 2: z = relu(a + b1) @ W2 (256 -> 2) -------------------
__global__ void k_gemm2(const float* __restrict__ W2, const float* __restrict__ b1) {
    int row = (blockIdx.x * blockDim.x + threadIdx.x) >> 5;
    int lane = threadIdx.x & 31;
    if (row >= NN) return;
    const float* ar = g_a + (size_t)row * HID;
    float acc0 = 0.f, acc1 = 0.f;
#pragma unroll
    for (int k = lane; k < HID; k += 32) {
        float v = fmaxf(ar[k] + b1[k], 0.f);    // bias+relu fused
        acc0 = fmaf(v, W2[k * 2 + 0], acc0);
        acc1 = fmaf(v, W2[k * 2 + 1], acc1);
    }
#pragma unroll
    for (int o = 16; o > 0; o >>= 1) {
        acc0 += __shfl_xor_sync(0xffffffffu, acc0, o);
        acc1 += __shfl_xor_sync(0xffffffffu, acc1, o);
    }
    if (lane == 0) {
        g_z[row * 2 + 0] = acc0;
        g_z[row * 2 + 1] = acc1;
    }
}

// out init with self-loop + bias: out[i,:] = dinv[i]^2 * z[i,:] + b2
__global__ void k_self_init_out(float* __restrict__ out, const float* __restrict__ b2) {
    int i = blockIdx.x * blockDim.x + threadIdx.x;
    if (i >= NN) return;
    float dv = g_deg[i];
    float s = dv * dv;
    out[i * 2 + 0] = s * g_z[i * 2 + 0] + b2[0];
    out[i * 2 + 1] = s * g_z[i * 2 + 1] + b2[1];
}

// per-edge scatter of 2 features
__global__ void k_edge_agg_out(const int* __restrict__ ei, float* __restrict__ out) {
    int e = blockIdx.x * blockDim.x + threadIdx.x;
    if (e >= EE) return;
    int sh = g_shift;
    int s = edge_src(ei, e, sh);
    int d = edge_dst(ei, e, sh);
    float nrm = g_deg[s] * g_deg[d];
    float2 v = reinterpret_cast<const float2*>(g_z)[s];
    red_add_v2(out + (size_t)d * 2, v.x * nrm, v.y * nrm);
}

// ---------------- launch -----------------------------------------------------
extern "C" void kernel_launch(void* const* d_in, const int* in_sizes, int n_in,
                              void* d_out, int out_size) {
    const float* x = nullptr;
    const float* W1 = nullptr;
    const float* b1 = nullptr;
    const float* W2 = nullptr;
    const float* b2 = nullptr;
    const int* ei = nullptr;
    for (int i = 0; i < n_in; i++) {
        switch (in_sizes[i]) {
            case NN * IN_DIM:      x  = (const float*)d_in[i]; break;
            case IN_DIM * HID:     W1 = (const float*)d_in[i]; break;
            case HID:              b1 = (const float*)d_in[i]; break;
            case HID * OUTD:       W2 = (const float*)d_in[i]; break;
            case OUTD:             b2 = (const float*)d_in[i]; break;
            case 2 * EE:           ei = (const int*)d_in[i]; break;
            default: break;
        }
    }
    float* out = (float*)d_out;

    float* d_h;   cudaGetSymbolAddress((void**)&d_h, g_h);
    float* d_a;   cudaGetSymbolAddress((void**)&d_a, g_a);
    float* d_deg; cudaGetSymbolAddress((void**)&d_deg, g_deg);

    const int T = 256;
    // edge dtype detection + degree / dinv
    k_detect<<<1, 32>>>(ei);
    k_deg_init<<<(NN + T - 1) / T, T>>>();
    k_deg_acc<<<(EE + T - 1) / T, T>>>(ei);
    k_dinv<<<(NN + T - 1) / T, T>>>();

    // GEMM1 (tf32 tensor cores): h = x @ W1, a = dinv^2 * h
    {
        dim3 grid((NN + BM - 1) / BM, HID / BN);
        k_mma_gemm<<<grid, 256>>>(x, W1, d_h, d_a, d_deg);
    }

    // aggregation 1 (RMW into a)
    {
        long long threads = (long long)EE * 32;
        k_edge_agg_hid<<<(unsigned)((threads + T - 1) / T), T>>>(ei);
    }

    // layer 2: transform first (A-hat commutes with per-node linear map)
    {
        long long threads = (long long)NN * 32;
        k_gemm2<<<(unsigned)((threads + T - 1) / T), T>>>(W2, b1);
    }
    k_self_init_out<<<(NN + T - 1) / T, T>>>(out, b2);
    k_edge_agg_out<<<(EE + T - 1) / T, T>>>(ei, out);

    (void)out_size;
}

// round 4
// speedup vs baseline: 2.2892x; 1.2672x over previous
#include <cuda_runtime.h>
#include <cuda_bf16.h>
#include <cstdint>

#define NN 50000
#define EE 1600000
#define IN_DIM 1000
#define HID 256
#define OUTD 2

// ---------------- scratch (device globals; no allocation allowed) ----------
__device__ float g_deg[NN];                // dinv (after k_dinv)
__device__ int   g_cnt[NN];                // in-degree histogram (no self-loop)
__device__ int   g_rowptr[NN + 1];         // CSR row pointers
__device__ int   g_wptr[NN];               // scatter cursors
__device__ int   g_csr_src[EE];            // CSR column (src) indices
__device__ float g_h[(size_t)NN * HID];    // X @ W1
__device__ float g_z[(size_t)NN * OUTD];   // relu(a+b1) @ W2
__device__ int   g_shift;                  // 0: edge_index int32, 1: int64

// ---------------- helpers ---------------------------------------------------
__device__ __forceinline__ void red_add_v2(float* p, float a, float b) {
    asm volatile("red.global.add.v2.f32 [%0], {%1,%2};"
                 :: "l"(p), "f"(a), "f"(b) : "memory");
}
__device__ __forceinline__ uint32_t f2tf32(float f) {
    uint32_t u;
    asm("cvt.rna.tf32.f32 %0, %1;" : "=r"(u) : "f"(f));
    return u;
}

// ---------------- edge dtype detection ---------------------------------------
__global__ void k_detect(const int* __restrict__ ei32) {
    int lane = threadIdx.x;
    unsigned any = 0;
    for (int base = 0; base < 2048; base += 32) {
        int v = ei32[2 * (base + lane) + 1];
        any |= __ballot_sync(0xffffffffu, v != 0);
    }
    if (lane == 0) g_shift = (any == 0) ? 1 : 0;
}
__device__ __forceinline__ int edge_src(const int* ei, int e, int sh) {
    return ei[(size_t)e << sh];
}
__device__ __forceinline__ int edge_dst(const int* ei, int e, int sh) {
    return ei[(size_t)(EE + e) << sh];
}

// ---------------- degree histogram / dinv -------------------------------------
__global__ void k_zero_cnt() {
    int i = blockIdx.x * blockDim.x + threadIdx.x;
    if (i < NN) g_cnt[i] = 0;
}
__global__ void k_deg_acc(const int* __restrict__ ei) {
    int e = blockIdx.x * blockDim.x + threadIdx.x;
    if (e < EE) {
        int sh = g_shift;
        atomicAdd(&g_cnt[edge_dst(ei, e, sh)], 1);
    }
}
__global__ void k_dinv() {
    int i = blockIdx.x * blockDim.x + threadIdx.x;
    if (i < NN) g_deg[i] = rsqrtf((float)(g_cnt[i] + 1));   // +1 self-loop
}

// ---------------- single-block exclusive scan (1024 threads, chunk=49) --------
__global__ void k_scan() {
    __shared__ int sums[1024];
    const int CH = 49;                        // 49*1024 = 50176 >= NN
    int t = threadIdx.x;
    int begN = t * CH;
    int endN = min(begN + CH, NN);
    int s = 0;
    for (int i = begN; i < endN; i++) s += g_cnt[i];
    sums[t] = s;
    __syncthreads();
    for (int off = 1; off < 1024; off <<= 1) {
        int v = (t >= off) ? sums[t - off] : 0;
        __syncthreads();
        sums[t] += v;
        __syncthreads();
    }
    int prefix = (t == 0) ? 0 : sums[t - 1];
    for (int i = begN; i < endN; i++) {
        g_rowptr[i] = prefix;
        g_wptr[i] = prefix;
        prefix += g_cnt[i];
    }
    if (t == 1023) g_rowptr[NN] = sums[1023];
}

// ---------------- CSR scatter --------------------------------------------------
__global__ void k_scatter(const int* __restrict__ ei) {
    int e = blockIdx.x * blockDim.x + threadIdx.x;
    if (e >= EE) return;
    int sh = g_shift;
    int s = edge_src(ei, e, sh);
    int d = edge_dst(ei, e, sh);
    int pos = atomicAdd(&g_wptr[d], 1);
    g_csr_src[pos] = s;
}

// ---------------- GEMM1: tf32 mma.sync, 128x128x16 tile ----------------------
#define BM 128
#define BN 128
#define BK 16
#define NIT ((IN_DIM + BK - 1) / BK)   // 63
#define AS_STRIDE 20
#define BS_STRIDE 132

__global__ __launch_bounds__(256)
void k_mma_gemm(const float* __restrict__ A, const float* __restrict__ B,
                float* __restrict__ C) {
    __shared__ uint32_t As[2][BM * AS_STRIDE];
    __shared__ uint32_t Bs[2][BK * BS_STRIDE];

    const int tid = threadIdx.x;
    const int bm = blockIdx.x * BM;
    const int bn = blockIdx.y * BN;

    const int warp = tid >> 5;
    const int lane = tid & 31;
    const int g = lane >> 2;
    const int t = lane & 3;
    const int warpM = warp >> 1;
    const int warpN = warp & 1;

    const int aRow0 = tid >> 2,          aQ0 = tid & 3;
    const int aRow1 = (tid + 256) >> 2,  aQ1 = (tid + 256) & 3;
    const int bK0 = tid >> 5,            bQ0 = tid & 31;
    const int bK1 = (tid + 256) >> 5,    bQ1 = (tid + 256) & 31;

    float acc[2][8][4];
#pragma unroll
    for (int mi = 0; mi < 2; mi++)
#pragma unroll
        for (int ni = 0; ni < 8; ni++)
#pragma unroll
            for (int c = 0; c < 4; c++) acc[mi][ni][c] = 0.f;

    float4 aStage[2], bStage[2];

    auto loadStage = [&](int k0) {
        const float4 z = make_float4(0.f, 0.f, 0.f, 0.f);
        int gr0 = bm + aRow0, gr1 = bm + aRow1;
        int ka0 = k0 + 4 * aQ0, ka1 = k0 + 4 * aQ1;
        aStage[0] = (gr0 < NN && ka0 < IN_DIM)
            ? *reinterpret_cast<const float4*>(A + (size_t)gr0 * IN_DIM + ka0) : z;
        aStage[1] = (gr1 < NN && ka1 < IN_DIM)
            ? *reinterpret_cast<const float4*>(A + (size_t)gr1 * IN_DIM + ka1) : z;
        int kb0 = k0 + bK0, kb1 = k0 + bK1;
        bStage[0] = (kb0 < IN_DIM)
            ? *reinterpret_cast<const float4*>(B + (size_t)kb0 * HID + bn + 4 * bQ0) : z;
        bStage[1] = (kb1 < IN_DIM)
            ? *reinterpret_cast<const float4*>(B + (size_t)kb1 * HID + bn + 4 * bQ1) : z;
    };

    auto storeStage = [&](int buf) {
        uint32_t* as = As[buf];
        uint32_t* bs = Bs[buf];
        as[aRow0 * AS_STRIDE + 4 * aQ0 + 0] = f2tf32(aStage[0].x);
        as[aRow0 * AS_STRIDE + 4 * aQ0 + 1] = f2tf32(aStage[0].y);
        as[aRow0 * AS_STRIDE + 4 * aQ0 + 2] = f2tf32(aStage[0].z);
        as[aRow0 * AS_STRIDE + 4 * aQ0 + 3] = f2tf32(aStage[0].w);
        as[aRow1 * AS_STRIDE + 4 * aQ1 + 0] = f2tf32(aStage[1].x);
        as[aRow1 * AS_STRIDE + 4 * aQ1 + 1] = f2tf32(aStage[1].y);
        as[aRow1 * AS_STRIDE + 4 * aQ1 + 2] = f2tf32(aStage[1].z);
        as[aRow1 * AS_STRIDE + 4 * aQ1 + 3] = f2tf32(aStage[1].w);
        bs[bK0 * BS_STRIDE + 4 * bQ0 + 0] = f2tf32(bStage[0].x);
        bs[bK0 * BS_STRIDE + 4 * bQ0 + 1] = f2tf32(bStage[0].y);
        bs[bK0 * BS_STRIDE + 4 * bQ0 + 2] = f2tf32(bStage[0].z);
        bs[bK0 * BS_STRIDE + 4 * bQ0 + 3] = f2tf32(bStage[0].w);
        bs[bK1 * BS_STRIDE + 4 * bQ1 + 0] = f2tf32(bStage[1].x);
        bs[bK1 * BS_STRIDE + 4 * bQ1 + 1] = f2tf32(bStage[1].y);
        bs[bK1 * BS_STRIDE + 4 * bQ1 + 2] = f2tf32(bStage[1].z);
        bs[bK1 * BS_STRIDE + 4 * bQ1 + 3] = f2tf32(bStage[1].w);
    };

    loadStage(0);
    storeStage(0);
    __syncthreads();

    int buf = 0;
    for (int it = 0; it < NIT; ++it) {
        if (it + 1 < NIT) loadStage((it + 1) * BK);

        const uint32_t* as = As[buf];
        const uint32_t* bs = Bs[buf];
#pragma unroll
        for (int k8 = 0; k8 < 2; k8++) {
            const int kk = k8 * 8;
            uint32_t afr[2][4];
#pragma unroll
            for (int mi = 0; mi < 2; mi++) {
                const int rb = warpM * 32 + mi * 16;
                afr[mi][0] = as[(rb + g    ) * AS_STRIDE + kk + t    ];
                afr[mi][1] = as[(rb + g + 8) * AS_STRIDE + kk + t    ];
                afr[mi][2] = as[(rb + g    ) * AS_STRIDE + kk + t + 4];
                afr[mi][3] = as[(rb + g + 8) * AS_STRIDE + kk + t + 4];
            }
            uint32_t bfr[8][2];
#pragma unroll
            for (int ni = 0; ni < 8; ni++) {
                const int n = warpN * 64 + ni * 8 + g;
                bfr[ni][0] = bs[(kk + t    ) * BS_STRIDE + n];
                bfr[ni][1] = bs[(kk + t + 4) * BS_STRIDE + n];
            }
#pragma unroll
            for (int mi = 0; mi < 2; mi++)
#pragma unroll
                for (int ni = 0; ni < 8; ni++) {
                    asm volatile(
                        "mma.sync.aligned.m16n8k8.row.col.f32.tf32.tf32.f32 "
                        "{%0,%1,%2,%3}, {%4,%5,%6,%7}, {%8,%9}, {%0,%1,%2,%3};"
                        : "+f"(acc[mi][ni][0]), "+f"(acc[mi][ni][1]),
                          "+f"(acc[mi][ni][2]), "+f"(acc[mi][ni][3])
                        : "r"(afr[mi][0]), "r"(afr[mi][1]),
                          "r"(afr[mi][2]), "r"(afr[mi][3]),
                          "r"(bfr[ni][0]), "r"(bfr[ni][1]));
                }
        }

        if (it + 1 < NIT) storeStage(buf ^ 1);
        __syncthreads();
        buf ^= 1;
    }

#pragma unroll
    for (int mi = 0; mi < 2; mi++) {
#pragma unroll
        for (int half = 0; half < 2; half++) {
            int r = bm + warpM * 32 + mi * 16 + g + half * 8;
            if (r >= NN) continue;
            size_t rowOff = (size_t)r * HID + bn + warpN * 64 + 2 * t;
#pragma unroll
            for (int ni = 0; ni < 8; ni++) {
                *reinterpret_cast<float2*>(C + rowOff + ni * 8) =
                    make_float2(acc[mi][ni][half * 2 + 0], acc[mi][ni][half * 2 + 1]);
            }
        }
    }
}

// ---------------- fused: CSR aggregate + bias + relu + W2 + out init ----------
// Warp per node. acc(lane) covers cols [4L..4L+3] and [128+4L..128+4L+3].
// a[d] = dinv[d] * ( sum_{s in N(d)} dinv[s]*h[s] + dinv[d]*h[d] )
// z[d] = relu(a[d]+b1) @ W2 ; out[d] = dinv[d]^2*z[d] + b2
__global__ __launch_bounds__(256)
void k_agg_fused(const float* __restrict__ b1, const float* __restrict__ W2,
                 const float* __restrict__ b2, float* __restrict__ out) {
    int node = (blockIdx.x * blockDim.x + threadIdx.x) >> 5;
    int lane = threadIdx.x & 31;
    if (node >= NN) return;

    int beg = g_rowptr[node];
    int end = g_rowptr[node + 1];
    float di = g_deg[node];

    float4 acc0 = make_float4(0.f, 0.f, 0.f, 0.f);
    float4 acc1 = make_float4(0.f, 0.f, 0.f, 0.f);

    for (int base = beg; base < end; base += 32) {
        int e = base + lane;
        int s = -1;
        float ds = 0.f;
        if (e < end) {
            s = __ldg(&g_csr_src[e]);
            ds = __ldg(&g_deg[s]);
        }
        int cnt = min(32, end - base);
        for (int j = 0; j < cnt; j++) {
            int sj = __shfl_sync(0xffffffffu, s, j);
            float w = __shfl_sync(0xffffffffu, ds, j);
            const float4* hrow = reinterpret_cast<const float4*>(g_h + (size_t)sj * HID);
            float4 v0 = __ldg(&hrow[lane]);
            float4 v1 = __ldg(&hrow[lane + 32]);
            acc0.x = fmaf(w, v0.x, acc0.x); acc0.y = fmaf(w, v0.y, acc0.y);
            acc0.z = fmaf(w, v0.z, acc0.z); acc0.w = fmaf(w, v0.w, acc0.w);
            acc1.x = fmaf(w, v1.x, acc1.x); acc1.y = fmaf(w, v1.y, acc1.y);
            acc1.z = fmaf(w, v1.z, acc1.z); acc1.w = fmaf(w, v1.w, acc1.w);
        }
    }

    // self-loop term
    {
        const float4* hrow = reinterpret_cast<const float4*>(g_h + (size_t)node * HID);
        float4 v0 = __ldg(&hrow[lane]);
        float4 v1 = __ldg(&hrow[lane + 32]);
        acc0.x = fmaf(di, v0.x, acc0.x); acc0.y = fmaf(di, v0.y, acc0.y);
        acc0.z = fmaf(di, v0.z, acc0.z); acc0.w = fmaf(di, v0.w, acc0.w);
        acc1.x = fmaf(di, v1.x, acc1.x); acc1.y = fmaf(di, v1.y, acc1.y);
        acc1.z = fmaf(di, v1.z, acc1.z); acc1.w = fmaf(di, v1.w, acc1.w);
    }

    // a = di * acc ; v = relu(a + b1) ; z = v @ W2 (warp reduce)
    float4 bb0 = __ldg(&reinterpret_cast<const float4*>(b1)[lane]);
    float4 bb1 = __ldg(&reinterpret_cast<const float4*>(b1)[lane + 32]);
    float v[8];
    v[0] = fmaxf(fmaf(di, acc0.x, bb0.x), 0.f);
    v[1] = fmaxf(fmaf(di, acc0.y, bb0.y), 0.f);
    v[2] = fmaxf(fmaf(di, acc0.z, bb0.z), 0.f);
    v[3] = fmaxf(fmaf(di, acc0.w, bb0.w), 0.f);
    v[4] = fmaxf(fmaf(di, acc1.x, bb1.x), 0.f);
    v[5] = fmaxf(fmaf(di, acc1.y, bb1.y), 0.f);
    v[6] = fmaxf(fmaf(di, acc1.z, bb1.z), 0.f);
    v[7] = fmaxf(fmaf(di, acc1.w, bb1.w), 0.f);

    // W2 rows for cols c0 = 4*lane.. and c1 = 128+4*lane..: each 8 consecutive floats
    float4 w0a = __ldg(&reinterpret_cast<const float4*>(W2)[2 * lane]);
    float4 w0b = __ldg(&reinterpret_cast<const float4*>(W2)[2 * lane + 1]);
    float4 w1a = __ldg(&reinterpret_cast<const float4*>(W2)[2 * (lane + 32)]);
    float4 w1b = __ldg(&reinterpret_cast<const float4*>(W2)[2 * (lane + 32) + 1]);

    float z0 = v[0] * w0a.x + v[1] * w0a.z + v[2] * w0b.x + v[3] * w0b.z
             + v[4] * w1a.x + v[5] * w1a.z + v[6] * w1b.x + v[7] * w1b.z;
    float z1 = v[0] * w0a.y + v[1] * w0a.w + v[2] * w0b.y + v[3] * w0b.w
             + v[4] * w1a.y + v[5] * w1a.w + v[6] * w1b.y + v[7] * w1b.w;

#pragma unroll
    for (int o = 16; o > 0; o >>= 1) {
        z0 += __shfl_xor_sync(0xffffffffu, z0, o);
        z1 += __shfl_xor_sync(0xffffffffu, z1, o);
    }
    if (lane == 0) {
        g_z[node * 2 + 0] = z0;
        g_z[node * 2 + 1] = z1;
        float s = di * di;
        out[node * 2 + 0] = fmaf(s, z0, __ldg(&b2[0]));
        out[node * 2 + 1] = fmaf(s, z1, __ldg(&b2[1]));
    }
}

// ---------------- final edge scatter of 2 features -----------------------------
__global__ void k_edge_agg_out(const int* __restrict__ ei, float* __restrict__ out) {
    int e = blockIdx.x * blockDim.x + threadIdx.x;
    if (e >= EE) return;
    int sh = g_shift;
    int s = edge_src(ei, e, sh);
    int d = edge_dst(ei, e, sh);
    float nrm = g_deg[s] * g_deg[d];
    float2 v = reinterpret_cast<const float2*>(g_z)[s];
    red_add_v2(out + (size_t)d * 2, v.x * nrm, v.y * nrm);
}

// ---------------- launch -----------------------------------------------------
extern "C" void kernel_launch(void* const* d_in, const int* in_sizes, int n_in,
                              void* d_out, int out_size) {
    const float* x = nullptr;
    const float* W1 = nullptr;
    const float* b1 = nullptr;
    const float* W2 = nullptr;
    const float* b2 = nullptr;
    const int* ei = nullptr;
    for (int i = 0; i < n_in; i++) {
        switch (in_sizes[i]) {
            case NN * IN_DIM:      x  = (const float*)d_in[i]; break;
            case IN_DIM * HID:     W1 = (const float*)d_in[i]; break;
            case HID:              b1 = (const float*)d_in[i]; break;
            case HID * OUTD:       W2 = (const float*)d_in[i]; break;
            case OUTD:             b2 = (const float*)d_in[i]; break;
            case 2 * EE:           ei = (const int*)d_in[i]; break;
            default: break;
        }
    }
    float* out = (float*)d_out;
    float* d_h; cudaGetSymbolAddress((void**)&d_h, g_h);

    const int T = 256;
    // edge dtype + CSR build
    k_detect<<<1, 32>>>(ei);
    k_zero_cnt<<<(NN + T - 1) / T, T>>>();
    k_deg_acc<<<(EE + T - 1) / T, T>>>(ei);
    k_dinv<<<(NN + T - 1) / T, T>>>();
    k_scan<<<1, 1024>>>();
    k_scatter<<<(EE + T - 1) / T, T>>>(ei);

    // GEMM1 (tf32 tensor cores): h = x @ W1
    {
        dim3 grid((NN + BM - 1) / BM, HID / BN);
        k_mma_gemm<<<grid, 256>>>(x, W1, d_h);
    }

    // fused: aggregate + bias + relu + W2 + out self-init
    {
        long long threads = (long long)NN * 32;
        k_agg_fused<<<(unsigned)((threads + T - 1) / T), T>>>(b1, W2, b2, out);
    }

    // final 2-feature edge scatter
    k_edge_agg_out<<<(EE + T - 1) / T, T>>>(ei, out);

    (void)out_size;
}

// round 5
// speedup vs baseline: 2.6096x; 1.1400x over previous
#include <cuda_runtime.h>
#include <cuda_fp16.h>
#include <cstdint>

#define NN 50000
#define EE 1600000
#define IN_DIM 1000
#define HID 256
#define OUTD 2

// ---------------- scratch (device globals; no allocation allowed) ----------
__device__ float  g_deg[NN];                // dinv (after k_dinv)
__device__ int    g_cnt[NN];                // in-degree histogram (no self-loop)
__device__ int    g_rowptr[NN + 1];         // CSR row pointers
__device__ int    g_wptr[NN];               // scatter cursors
__device__ int    g_csr_src[EE];            // CSR column (src) indices
__device__ __half g_h[(size_t)NN * HID];    // X @ W1  (fp16)
__device__ float  g_z[(size_t)NN * OUTD];   // relu(a+b1) @ W2
__device__ int    g_shift;                  // 0: edge_index int32, 1: int64

// ---------------- helpers ---------------------------------------------------
__device__ __forceinline__ void red_add_v2(float* p, float a, float b) {
    asm volatile("red.global.add.v2.f32 [%0], {%1,%2};"
                 :: "l"(p), "f"(a), "f"(b) : "memory");
}
__device__ __forceinline__ uint32_t f2tf32(float f) {
    uint32_t u;
    asm("cvt.rna.tf32.f32 %0, %1;" : "=r"(u) : "f"(f));
    return u;
}

// ---------------- edge dtype detection ---------------------------------------
__global__ void k_detect(const int* __restrict__ ei32) {
    int lane = threadIdx.x;
    unsigned any = 0;
    for (int base = 0; base < 2048; base += 32) {
        int v = ei32[2 * (base + lane) + 1];
        any |= __ballot_sync(0xffffffffu, v != 0);
    }
    if (lane == 0) g_shift = (any == 0) ? 1 : 0;
}
__device__ __forceinline__ int edge_src(const int* ei, int e, int sh) {
    return ei[(size_t)e << sh];
}
__device__ __forceinline__ int edge_dst(const int* ei, int e, int sh) {
    return ei[(size_t)(EE + e) << sh];
}

// ---------------- degree histogram / dinv -------------------------------------
__global__ void k_zero_cnt() {
    int i = blockIdx.x * blockDim.x + threadIdx.x;
    if (i < NN) g_cnt[i] = 0;
}
__global__ void k_deg_acc(const int* __restrict__ ei) {
    int e = blockIdx.x * blockDim.x + threadIdx.x;
    if (e < EE) {
        int sh = g_shift;
        atomicAdd(&g_cnt[edge_dst(ei, e, sh)], 1);
    }
}
__global__ void k_dinv() {
    int i = blockIdx.x * blockDim.x + threadIdx.x;
    if (i < NN) g_deg[i] = rsqrtf((float)(g_cnt[i] + 1));   // +1 self-loop
}

// ---------------- single-block exclusive scan (1024 threads, chunk=49) --------
__global__ void k_scan() {
    __shared__ int sums[1024];
    const int CH = 49;
    int t = threadIdx.x;
    int begN = t * CH;
    int endN = min(begN + CH, NN);
    int s = 0;
    for (int i = begN; i < endN; i++) s += g_cnt[i];
    sums[t] = s;
    __syncthreads();
    for (int off = 1; off < 1024; off <<= 1) {
        int v = (t >= off) ? sums[t - off] : 0;
        __syncthreads();
        sums[t] += v;
        __syncthreads();
    }
    int prefix = (t == 0) ? 0 : sums[t - 1];
    for (int i = begN; i < endN; i++) {
        g_rowptr[i] = prefix;
        g_wptr[i] = prefix;
        prefix += g_cnt[i];
    }
    if (t == 1023) g_rowptr[NN] = sums[1023];
}

// ---------------- CSR scatter --------------------------------------------------
__global__ void k_scatter(const int* __restrict__ ei) {
    int e = blockIdx.x * blockDim.x + threadIdx.x;
    if (e >= EE) return;
    int sh = g_shift;
    int s = edge_src(ei, e, sh);
    int d = edge_dst(ei, e, sh);
    int pos = atomicAdd(&g_wptr[d], 1);
    g_csr_src[pos] = s;
}

// ---------------- GEMM1: tf32 mma.sync, 128x128x16 tile, fp16 output ---------
#define BM 128
#define BN 128
#define BK 16
#define NIT ((IN_DIM + BK - 1) / BK)   // 63
#define AS_STRIDE 20
#define BS_STRIDE 132

__global__ __launch_bounds__(256)
void k_mma_gemm(const float* __restrict__ A, const float* __restrict__ B,
                __half* __restrict__ Ch) {
    __shared__ uint32_t As[2][BM * AS_STRIDE];
    __shared__ uint32_t Bs[2][BK * BS_STRIDE];

    const int tid = threadIdx.x;
    const int bm = blockIdx.x * BM;
    const int bn = blockIdx.y * BN;

    const int warp = tid >> 5;
    const int lane = tid & 31;
    const int g = lane >> 2;
    const int t = lane & 3;
    const int warpM = warp >> 1;
    const int warpN = warp & 1;

    const int aRow0 = tid >> 2,          aQ0 = tid & 3;
    const int aRow1 = (tid + 256) >> 2,  aQ1 = (tid + 256) & 3;
    const int bK0 = tid >> 5,            bQ0 = tid & 31;
    const int bK1 = (tid + 256) >> 5,    bQ1 = (tid + 256) & 31;

    float acc[2][8][4];
#pragma unroll
    for (int mi = 0; mi < 2; mi++)
#pragma unroll
        for (int ni = 0; ni < 8; ni++)
#pragma unroll
            for (int c = 0; c < 4; c++) acc[mi][ni][c] = 0.f;

    float4 aStage[2], bStage[2];

    auto loadStage = [&](int k0) {
        const float4 z = make_float4(0.f, 0.f, 0.f, 0.f);
        int gr0 = bm + aRow0, gr1 = bm + aRow1;
        int ka0 = k0 + 4 * aQ0, ka1 = k0 + 4 * aQ1;
        aStage[0] = (gr0 < NN && ka0 < IN_DIM)
            ? *reinterpret_cast<const float4*>(A + (size_t)gr0 * IN_DIM + ka0) : z;
        aStage[1] = (gr1 < NN && ka1 < IN_DIM)
            ? *reinterpret_cast<const float4*>(A + (size_t)gr1 * IN_DIM + ka1) : z;
        int kb0 = k0 + bK0, kb1 = k0 + bK1;
        bStage[0] = (kb0 < IN_DIM)
            ? *reinterpret_cast<const float4*>(B + (size_t)kb0 * HID + bn + 4 * bQ0) : z;
        bStage[1] = (kb1 < IN_DIM)
            ? *reinterpret_cast<const float4*>(B + (size_t)kb1 * HID + bn + 4 * bQ1) : z;
    };

    auto storeStage = [&](int buf) {
        uint32_t* as = As[buf];
        uint32_t* bs = Bs[buf];
        as[aRow0 * AS_STRIDE + 4 * aQ0 + 0] = f2tf32(aStage[0].x);
        as[aRow0 * AS_STRIDE + 4 * aQ0 + 1] = f2tf32(aStage[0].y);
        as[aRow0 * AS_STRIDE + 4 * aQ0 + 2] = f2tf32(aStage[0].z);
        as[aRow0 * AS_STRIDE + 4 * aQ0 + 3] = f2tf32(aStage[0].w);
        as[aRow1 * AS_STRIDE + 4 * aQ1 + 0] = f2tf32(aStage[1].x);
        as[aRow1 * AS_STRIDE + 4 * aQ1 + 1] = f2tf32(aStage[1].y);
        as[aRow1 * AS_STRIDE + 4 * aQ1 + 2] = f2tf32(aStage[1].z);
        as[aRow1 * AS_STRIDE + 4 * aQ1 + 3] = f2tf32(aStage[1].w);
        bs[bK0 * BS_STRIDE + 4 * bQ0 + 0] = f2tf32(bStage[0].x);
        bs[bK0 * BS_STRIDE + 4 * bQ0 + 1] = f2tf32(bStage[0].y);
        bs[bK0 * BS_STRIDE + 4 * bQ0 + 2] = f2tf32(bStage[0].z);
        bs[bK0 * BS_STRIDE + 4 * bQ0 + 3] = f2tf32(bStage[0].w);
        bs[bK1 * BS_STRIDE + 4 * bQ1 + 0] = f2tf32(bStage[1].x);
        bs[bK1 * BS_STRIDE + 4 * bQ1 + 1] = f2tf32(bStage[1].y);
        bs[bK1 * BS_STRIDE + 4 * bQ1 + 2] = f2tf32(bStage[1].z);
        bs[bK1 * BS_STRIDE + 4 * bQ1 + 3] = f2tf32(bStage[1].w);
    };

    loadStage(0);
    storeStage(0);
    __syncthreads();

    int buf = 0;
    for (int it = 0; it < NIT; ++it) {
        if (it + 1 < NIT) loadStage((it + 1) * BK);

        const uint32_t* as = As[buf];
        const uint32_t* bs = Bs[buf];
#pragma unroll
        for (int k8 = 0; k8 < 2; k8++) {
            const int kk = k8 * 8;
            uint32_t afr[2][4];
#pragma unroll
            for (int mi = 0; mi < 2; mi++) {
                const int rb = warpM * 32 + mi * 16;
                afr[mi][0] = as[(rb + g    ) * AS_STRIDE + kk + t    ];
                afr[mi][1] = as[(rb + g + 8) * AS_STRIDE + kk + t    ];
                afr[mi][2] = as[(rb + g    ) * AS_STRIDE + kk + t + 4];
                afr[mi][3] = as[(rb + g + 8) * AS_STRIDE + kk + t + 4];
            }
            uint32_t bfr[8][2];
#pragma unroll
            for (int ni = 0; ni < 8; ni++) {
                const int n = warpN * 64 + ni * 8 + g;
                bfr[ni][0] = bs[(kk + t    ) * BS_STRIDE + n];
                bfr[ni][1] = bs[(kk + t + 4) * BS_STRIDE + n];
            }
#pragma unroll
            for (int mi = 0; mi < 2; mi++)
#pragma unroll
                for (int ni = 0; ni < 8; ni++) {
                    asm volatile(
                        "mma.sync.aligned.m16n8k8.row.col.f32.tf32.tf32.f32 "
                        "{%0,%1,%2,%3}, {%4,%5,%6,%7}, {%8,%9}, {%0,%1,%2,%3};"
                        : "+f"(acc[mi][ni][0]), "+f"(acc[mi][ni][1]),
                          "+f"(acc[mi][ni][2]), "+f"(acc[mi][ni][3])
                        : "r"(afr[mi][0]), "r"(afr[mi][1]),
                          "r"(afr[mi][2]), "r"(afr[mi][3]),
                          "r"(bfr[ni][0]), "r"(bfr[ni][1]));
                }
        }

        if (it + 1 < NIT) storeStage(buf ^ 1);
        __syncthreads();
        buf ^= 1;
    }

    // epilogue: h (fp16)
#pragma unroll
    for (int mi = 0; mi < 2; mi++) {
#pragma unroll
        for (int half = 0; half < 2; half++) {
            int r = bm + warpM * 32 + mi * 16 + g + half * 8;
            if (r >= NN) continue;
            size_t rowOff = (size_t)r * HID + bn + warpN * 64 + 2 * t;
#pragma unroll
            for (int ni = 0; ni < 8; ni++) {
                __half2 hv = __floats2half2_rn(acc[mi][ni][half * 2 + 0],
                                               acc[mi][ni][half * 2 + 1]);
                *reinterpret_cast<__half2*>(Ch + rowOff + ni * 8) = hv;
            }
        }
    }
}

// ---------------- fused: CSR aggregate + bias + relu + W2 + out init ----------
// Warp per node; lane covers cols [8L .. 8L+7] (one uint4 = 8 fp16 per source row).
__global__ __launch_bounds__(256)
void k_agg_fused(const float* __restrict__ b1, const float* __restrict__ W2,
                 const float* __restrict__ b2, float* __restrict__ out) {
    int node = (blockIdx.x * blockDim.x + threadIdx.x) >> 5;
    int lane = threadIdx.x & 31;
    if (node >= NN) return;

    int beg = g_rowptr[node];
    int end = g_rowptr[node + 1];
    float di = g_deg[node];

    float acc[8];
#pragma unroll
    for (int c = 0; c < 8; c++) acc[c] = 0.f;

    auto accum = [&](int srow, float w) {
        const uint4* hrow = reinterpret_cast<const uint4*>(g_h + (size_t)srow * HID);
        uint4 u = __ldg(&hrow[lane]);
        float2 f0 = __half22float2(*reinterpret_cast<__half2*>(&u.x));
        float2 f1 = __half22float2(*reinterpret_cast<__half2*>(&u.y));
        float2 f2 = __half22float2(*reinterpret_cast<__half2*>(&u.z));
        float2 f3 = __half22float2(*reinterpret_cast<__half2*>(&u.w));
        acc[0] = fmaf(w, f0.x, acc[0]); acc[1] = fmaf(w, f0.y, acc[1]);
        acc[2] = fmaf(w, f1.x, acc[2]); acc[3] = fmaf(w, f1.y, acc[3]);
        acc[4] = fmaf(w, f2.x, acc[4]); acc[5] = fmaf(w, f2.y, acc[5]);
        acc[6] = fmaf(w, f3.x, acc[6]); acc[7] = fmaf(w, f3.y, acc[7]);
    };

    for (int base = beg; base < end; base += 32) {
        int e = base + lane;
        int s = -1;
        float ds = 0.f;
        if (e < end) {
            s = __ldg(&g_csr_src[e]);
            ds = __ldg(&g_deg[s]);
        }
        int cnt = min(32, end - base);
        for (int j = 0; j < cnt; j++) {
            int sj = __shfl_sync(0xffffffffu, s, j);
            float w = __shfl_sync(0xffffffffu, ds, j);
            accum(sj, w);
        }
    }
    accum(node, di);   // self-loop

    // v = relu(di*acc + b1)
    float4 bb0 = __ldg(&reinterpret_cast<const float4*>(b1)[2 * lane]);
    float4 bb1 = __ldg(&reinterpret_cast<const float4*>(b1)[2 * lane + 1]);
    float v[8];
    v[0] = fmaxf(fmaf(di, acc[0], bb0.x), 0.f);
    v[1] = fmaxf(fmaf(di, acc[1], bb0.y), 0.f);
    v[2] = fmaxf(fmaf(di, acc[2], bb0.z), 0.f);
    v[3] = fmaxf(fmaf(di, acc[3], bb0.w), 0.f);
    v[4] = fmaxf(fmaf(di, acc[4], bb1.x), 0.f);
    v[5] = fmaxf(fmaf(di, acc[5], bb1.y), 0.f);
    v[6] = fmaxf(fmaf(di, acc[6], bb1.z), 0.f);
    v[7] = fmaxf(fmaf(di, acc[7], bb1.w), 0.f);

    // z = v @ W2 : W2 float4 idx 4L+k holds rows (8L+2k, 8L+2k+1)
    float z0 = 0.f, z1 = 0.f;
#pragma unroll
    for (int k = 0; k < 4; k++) {
        float4 w = __ldg(&reinterpret_cast<const float4*>(W2)[4 * lane + k]);
        z0 = fmaf(v[2 * k], w.x, fmaf(v[2 * k + 1], w.z, z0));
        z1 = fmaf(v[2 * k], w.y, fmaf(v[2 * k + 1], w.w, z1));
    }
#pragma unroll
    for (int o = 16; o > 0; o >>= 1) {
        z0 += __shfl_xor_sync(0xffffffffu, z0, o);
        z1 += __shfl_xor_sync(0xffffffffu, z1, o);
    }
    if (lane == 0) {
        g_z[node * 2 + 0] = z0;
        g_z[node * 2 + 1] = z1;
        float s = di * di;
        out[node * 2 + 0] = fmaf(s, z0, __ldg(&b2[0]));
        out[node * 2 + 1] = fmaf(s, z1, __ldg(&b2[1]));
    }
}

// ---------------- final edge scatter of 2 features -----------------------------
__global__ void k_edge_agg_out(const int* __restrict__ ei, float* __restrict__ out) {
    int e = blockIdx.x * blockDim.x + threadIdx.x;
    if (e >= EE) return;
    int sh = g_shift;
    int s = edge_src(ei, e, sh);
    int d = edge_dst(ei, e, sh);
    float nrm = g_deg[s] * g_deg[d];
    float2 v = reinterpret_cast<const float2*>(g_z)[s];
    red_add_v2(out + (size_t)d * 2, v.x * nrm, v.y * nrm);
}

// ---------------- launch -----------------------------------------------------
extern "C" void kernel_launch(void* const* d_in, const int* in_sizes, int n_in,
                              void* d_out, int out_size) {
    const float* x = nullptr;
    const float* W1 = nullptr;
    const float* b1 = nullptr;
    const float* W2 = nullptr;
    const float* b2 = nullptr;
    const int* ei = nullptr;
    for (int i = 0; i < n_in; i++) {
        switch (in_sizes[i]) {
            case NN * IN_DIM:      x  = (const float*)d_in[i]; break;
            case IN_DIM * HID:     W1 = (const float*)d_in[i]; break;
            case HID:              b1 = (const float*)d_in[i]; break;
            case HID * OUTD:       W2 = (const float*)d_in[i]; break;
            case OUTD:             b2 = (const float*)d_in[i]; break;
            case 2 * EE:           ei = (const int*)d_in[i]; break;
            default: break;
        }
    }
    float* out = (float*)d_out;
    __half* d_h; cudaGetSymbolAddress((void**)&d_h, g_h);

    // side stream + events for CSR/GEMM overlap (created once, host-side only)
    static cudaStream_t s2 = nullptr;
    static cudaEvent_t evFork = nullptr, evJoin = nullptr;
    if (!s2) {
        cudaStreamCreateWithFlags(&s2, cudaStreamNonBlocking);
        cudaEventCreateWithFlags(&evFork, cudaEventDisableTiming);
        cudaEventCreateWithFlags(&evJoin, cudaEventDisableTiming);
    }

    const int T = 256;

    // edge dtype detection (needed by both branches)
    k_detect<<<1, 32>>>(ei);

    // fork: CSR build on s2, GEMM on main stream
    cudaEventRecord(evFork, 0);
    cudaStreamWaitEvent(s2, evFork, 0);

    k_zero_cnt<<<(NN + T - 1) / T, T, 0, s2>>>();
    k_deg_acc<<<(EE + T - 1) / T, T, 0, s2>>>(ei);
    k_dinv<<<(NN + T - 1) / T, T, 0, s2>>>();
    k_scan<<<1, 1024, 0, s2>>>();
    k_scatter<<<(EE + T - 1) / T, T, 0, s2>>>(ei);
    cudaEventRecord(evJoin, s2);

    // GEMM1 (tf32 tensor cores): h = x @ W1 (fp16 output)
    {
        dim3 grid((NN + BM - 1) / BM, HID / BN);
        k_mma_gemm<<<grid, 256>>>(x, W1, d_h);
    }

    // join: aggregation needs CSR + dinv + h
    cudaStreamWaitEvent(0, evJoin, 0);

    {
        long long threads = (long long)NN * 32;
        k_agg_fused<<<(unsigned)((threads + T - 1) / T), T>>>(b1, W2, b2, out);
    }
    k_edge_agg_out<<<(EE + T - 1) / T, T>>>(ei, out);

    (void)out_size;
}

// round 6
// speedup vs baseline: 2.7098x; 1.0384x over previous
#include <cuda_runtime.h>
#include <cuda_fp16.h>
#include <cstdint>

#define NN 50000
#define EE 1600000
#define IN_DIM 1000
#define HID 256
#define OUTD 2

// ---------------- scratch (device globals; no allocation allowed) ----------
__device__ float  g_deg[NN];                // dinv (after k_dinv)
__device__ int    g_cnt[NN];                // in-degree histogram (no self-loop)
__device__ int    g_rowptr[NN + 1];         // CSR row pointers
__device__ int    g_wptr[NN];               // scatter cursors
__device__ int    g_csr_src[EE];            // CSR column (src) indices
__device__ __half g_h[(size_t)NN * HID];    // X @ W1  (fp16)
__device__ float  g_z[(size_t)NN * OUTD];   // relu(a+b1) @ W2
__device__ int    g_shift;                  // 0: edge_index int32, 1: int64

// ---------------- helpers ---------------------------------------------------
__device__ __forceinline__ void red_add_v2(float* p, float a, float b) {
    asm volatile("red.global.add.v2.f32 [%0], {%1,%2};"
                 :: "l"(p), "f"(a), "f"(b) : "memory");
}
__device__ __forceinline__ void cp_async16(void* smem_dst, const void* gsrc, bool valid) {
    uint32_t saddr = (uint32_t)__cvta_generic_to_shared(smem_dst);
    int sz = valid ? 16 : 0;
    asm volatile("cp.async.cg.shared.global [%0], [%1], 16, %2;"
                 :: "r"(saddr), "l"(gsrc), "r"(sz));
}
__device__ __forceinline__ void cp_async_commit() {
    asm volatile("cp.async.commit_group;");
}

// ---------------- edge dtype detection ---------------------------------------
__global__ void k_detect(const int* __restrict__ ei32) {
    int lane = threadIdx.x;
    unsigned any = 0;
    for (int base = 0; base < 2048; base += 32) {
        int v = ei32[2 * (base + lane) + 1];
        any |= __ballot_sync(0xffffffffu, v != 0);
    }
    if (lane == 0) g_shift = (any == 0) ? 1 : 0;
}
__device__ __forceinline__ int edge_src(const int* ei, int e, int sh) {
    return ei[(size_t)e << sh];
}
__device__ __forceinline__ int edge_dst(const int* ei, int e, int sh) {
    return ei[(size_t)(EE + e) << sh];
}

// ---------------- degree histogram / dinv -------------------------------------
__global__ void k_zero_cnt() {
    int i = blockIdx.x * blockDim.x + threadIdx.x;
    if (i < NN) g_cnt[i] = 0;
}
__global__ void k_deg_acc(const int* __restrict__ ei) {
    int e = blockIdx.x * blockDim.x + threadIdx.x;
    if (e < EE) {
        int sh = g_shift;
        atomicAdd(&g_cnt[edge_dst(ei, e, sh)], 1);
    }
}
__global__ void k_dinv() {
    int i = blockIdx.x * blockDim.x + threadIdx.x;
    if (i < NN) g_deg[i] = rsqrtf((float)(g_cnt[i] + 1));   // +1 self-loop
}

// ---------------- single-block exclusive scan (1024 threads, chunk=49) --------
__global__ void k_scan() {
    __shared__ int sums[1024];
    const int CH = 49;
    int t = threadIdx.x;
    int begN = t * CH;
    int endN = min(begN + CH, NN);
    int s = 0;
    for (int i = begN; i < endN; i++) s += g_cnt[i];
    sums[t] = s;
    __syncthreads();
    for (int off = 1; off < 1024; off <<= 1) {
        int v = (t >= off) ? sums[t - off] : 0;
        __syncthreads();
        sums[t] += v;
        __syncthreads();
    }
    int prefix = (t == 0) ? 0 : sums[t - 1];
    for (int i = begN; i < endN; i++) {
        g_rowptr[i] = prefix;
        g_wptr[i] = prefix;
        prefix += g_cnt[i];
    }
    if (t == 1023) g_rowptr[NN] = sums[1023];
}

// ---------------- CSR scatter --------------------------------------------------
__global__ void k_scatter(const int* __restrict__ ei) {
    int e = blockIdx.x * blockDim.x + threadIdx.x;
    if (e >= EE) return;
    int sh = g_shift;
    int s = edge_src(ei, e, sh);
    int d = edge_dst(ei, e, sh);
    int pos = atomicAdd(&g_wptr[d], 1);
    g_csr_src[pos] = s;
}

// ---------------- GEMM1: tf32 mma.sync + cp.async 3-stage, fp16 output --------
#define BM 128
#define BN 128
#define BK 16
#define NIT ((IN_DIM + BK - 1) / BK)   // 63
#define AS_STRIDE 20                    // floats; 80B rows -> 16B aligned
#define BS_STRIDE 132                   // floats; 528B rows -> 16B aligned
#define STAGES 3
#define A_STAGE (BM * AS_STRIDE)
#define B_STAGE (BK * BS_STRIDE)
#define SMEM_BYTES ((STAGES * (A_STAGE + B_STAGE)) * 4)

__global__ __launch_bounds__(256)
void k_mma_gemm(const float* __restrict__ A, const float* __restrict__ B,
                __half* __restrict__ Ch) {
    extern __shared__ float sm[];
    float* AsBase = sm;
    float* BsBase = sm + STAGES * A_STAGE;

    const int tid = threadIdx.x;
    const int bm = blockIdx.x * BM;
    const int bn = blockIdx.y * BN;

    const int warp = tid >> 5;
    const int lane = tid & 31;
    const int g = lane >> 2;
    const int t = lane & 3;
    const int warpM = warp >> 1;
    const int warpN = warp & 1;

    const int aRow0 = tid >> 2,          aQ0 = tid & 3;
    const int aRow1 = (tid + 256) >> 2,  aQ1 = (tid + 256) & 3;
    const int bK0 = tid >> 5,            bQ0 = tid & 31;
    const int bK1 = (tid + 256) >> 5,    bQ1 = (tid + 256) & 31;

    auto issueStage = [&](int it) {
        int buf = it % STAGES;
        int k0 = it * BK;
        float* as = AsBase + buf * A_STAGE;
        float* bs = BsBase + buf * B_STAGE;
        int gr0 = bm + aRow0, gr1 = bm + aRow1;
        int ka0 = k0 + 4 * aQ0, ka1 = k0 + 4 * aQ1;
        cp_async16(as + aRow0 * AS_STRIDE + 4 * aQ0,
                   A + (size_t)gr0 * IN_DIM + ka0, gr0 < NN && ka0 < IN_DIM);
        cp_async16(as + aRow1 * AS_STRIDE + 4 * aQ1,
                   A + (size_t)gr1 * IN_DIM + ka1, gr1 < NN && ka1 < IN_DIM);
        int kb0 = k0 + bK0, kb1 = k0 + bK1;
        cp_async16(bs + bK0 * BS_STRIDE + 4 * bQ0,
                   B + (size_t)kb0 * HID + bn + 4 * bQ0, kb0 < IN_DIM);
        cp_async16(bs + bK1 * BS_STRIDE + 4 * bQ1,
                   B + (size_t)kb1 * HID + bn + 4 * bQ1, kb1 < IN_DIM);
        cp_async_commit();
    };

    float acc[2][8][4];
#pragma unroll
    for (int mi = 0; mi < 2; mi++)
#pragma unroll
        for (int ni = 0; ni < 8; ni++)
#pragma unroll
            for (int c = 0; c < 4; c++) acc[mi][ni][c] = 0.f;

    issueStage(0);
    issueStage(1);

    for (int it = 0; it < NIT; ++it) {
        asm volatile("cp.async.wait_group 1;");
        __syncthreads();
        if (it + 2 < NIT) issueStage(it + 2);

        const int buf = it % STAGES;
        const uint32_t* as = reinterpret_cast<const uint32_t*>(AsBase + buf * A_STAGE);
        const uint32_t* bs = reinterpret_cast<const uint32_t*>(BsBase + buf * B_STAGE);
#pragma unroll
        for (int k8 = 0; k8 < 2; k8++) {
            const int kk = k8 * 8;
            uint32_t afr[2][4];
#pragma unroll
            for (int mi = 0; mi < 2; mi++) {
                const int rb = warpM * 32 + mi * 16;
                afr[mi][0] = as[(rb + g    ) * AS_STRIDE + kk + t    ];
                afr[mi][1] = as[(rb + g + 8) * AS_STRIDE + kk + t    ];
                afr[mi][2] = as[(rb + g    ) * AS_STRIDE + kk + t + 4];
                afr[mi][3] = as[(rb + g + 8) * AS_STRIDE + kk + t + 4];
            }
            uint32_t bfr[8][2];
#pragma unroll
            for (int ni = 0; ni < 8; ni++) {
                const int n = warpN * 64 + ni * 8 + g;
                bfr[ni][0] = bs[(kk + t    ) * BS_STRIDE + n];
                bfr[ni][1] = bs[(kk + t + 4) * BS_STRIDE + n];
            }
#pragma unroll
            for (int mi = 0; mi < 2; mi++)
#pragma unroll
                for (int ni = 0; ni < 8; ni++) {
                    asm volatile(
                        "mma.sync.aligned.m16n8k8.row.col.f32.tf32.tf32.f32 "
                        "{%0,%1,%2,%3}, {%4,%5,%6,%7}, {%8,%9}, {%0,%1,%2,%3};"
                        : "+f"(acc[mi][ni][0]), "+f"(acc[mi][ni][1]),
                          "+f"(acc[mi][ni][2]), "+f"(acc[mi][ni][3])
                        : "r"(afr[mi][0]), "r"(afr[mi][1]),
                          "r"(afr[mi][2]), "r"(afr[mi][3]),
                          "r"(bfr[ni][0]), "r"(bfr[ni][1]));
                }
        }
    }

    // epilogue: h (fp16)
#pragma unroll
    for (int mi = 0; mi < 2; mi++) {
#pragma unroll
        for (int half = 0; half < 2; half++) {
            int r = bm + warpM * 32 + mi * 16 + g + half * 8;
            if (r >= NN) continue;
            size_t rowOff = (size_t)r * HID + bn + warpN * 64 + 2 * t;
#pragma unroll
            for (int ni = 0; ni < 8; ni++) {
                __half2 hv = __floats2half2_rn(acc[mi][ni][half * 2 + 0],
                                               acc[mi][ni][half * 2 + 1]);
                *reinterpret_cast<__half2*>(Ch + rowOff + ni * 8) = hv;
            }
        }
    }
}

// ---------------- fused: CSR aggregate + bias + relu + W2 + out init ----------
// Warp per node; lane covers cols [8L .. 8L+7]; inner gather unrolled x4 (MLP=4).
__global__ __launch_bounds__(256)
void k_agg_fused(const float* __restrict__ b1, const float* __restrict__ W2,
                 const float* __restrict__ b2, float* __restrict__ out) {
    int node = (blockIdx.x * blockDim.x + threadIdx.x) >> 5;
    int lane = threadIdx.x & 31;
    if (node >= NN) return;

    int beg = g_rowptr[node];
    int end = g_rowptr[node + 1];
    float di = g_deg[node];

    float acc[8];
#pragma unroll
    for (int c = 0; c < 8; c++) acc[c] = 0.f;

    auto accumU = [&](uint4 u, float w) {
        float2 f0 = __half22float2(*reinterpret_cast<__half2*>(&u.x));
        float2 f1 = __half22float2(*reinterpret_cast<__half2*>(&u.y));
        float2 f2 = __half22float2(*reinterpret_cast<__half2*>(&u.z));
        float2 f3 = __half22float2(*reinterpret_cast<__half2*>(&u.w));
        acc[0] = fmaf(w, f0.x, acc[0]); acc[1] = fmaf(w, f0.y, acc[1]);
        acc[2] = fmaf(w, f1.x, acc[2]); acc[3] = fmaf(w, f1.y, acc[3]);
        acc[4] = fmaf(w, f2.x, acc[4]); acc[5] = fmaf(w, f2.y, acc[5]);
        acc[6] = fmaf(w, f3.x, acc[6]); acc[7] = fmaf(w, f3.y, acc[7]);
    };

    for (int base = beg; base < end; base += 32) {
        int e = base + lane;
        int s = -1;
        float ds = 0.f;
        if (e < end) {
            s = __ldg(&g_csr_src[e]);
            ds = __ldg(&g_deg[s]);
        }
        int cnt = min(32, end - base);
        int j = 0;
        for (; j + 4 <= cnt; j += 4) {
            int s0 = __shfl_sync(0xffffffffu, s, j);
            int s1 = __shfl_sync(0xffffffffu, s, j + 1);
            int s2 = __shfl_sync(0xffffffffu, s, j + 2);
            int s3 = __shfl_sync(0xffffffffu, s, j + 3);
            float w0 = __shfl_sync(0xffffffffu, ds, j);
            float w1 = __shfl_sync(0xffffffffu, ds, j + 1);
            float w2 = __shfl_sync(0xffffffffu, ds, j + 2);
            float w3 = __shfl_sync(0xffffffffu, ds, j + 3);
            uint4 u0 = __ldg(&reinterpret_cast<const uint4*>(g_h + (size_t)s0 * HID)[lane]);
            uint4 u1 = __ldg(&reinterpret_cast<const uint4*>(g_h + (size_t)s1 * HID)[lane]);
            uint4 u2 = __ldg(&reinterpret_cast<const uint4*>(g_h + (size_t)s2 * HID)[lane]);
            uint4 u3 = __ldg(&reinterpret_cast<const uint4*>(g_h + (size_t)s3 * HID)[lane]);
            accumU(u0, w0); accumU(u1, w1); accumU(u2, w2); accumU(u3, w3);
        }
        for (; j < cnt; j++) {
            int sj = __shfl_sync(0xffffffffu, s, j);
            float w = __shfl_sync(0xffffffffu, ds, j);
            uint4 u = __ldg(&reinterpret_cast<const uint4*>(g_h + (size_t)sj * HID)[lane]);
            accumU(u, w);
        }
    }
    {   // self-loop
        uint4 u = __ldg(&reinterpret_cast<const uint4*>(g_h + (size_t)node * HID)[lane]);
        accumU(u, di);
    }

    // v = relu(di*acc + b1)
    float4 bb0 = __ldg(&reinterpret_cast<const float4*>(b1)[2 * lane]);
    float4 bb1 = __ldg(&reinterpret_cast<const float4*>(b1)[2 * lane + 1]);
    float v[8];
    v[0] = fmaxf(fmaf(di, acc[0], bb0.x), 0.f);
    v[1] = fmaxf(fmaf(di, acc[1], bb0.y), 0.f);
    v[2] = fmaxf(fmaf(di, acc[2], bb0.z), 0.f);
    v[3] = fmaxf(fmaf(di, acc[3], bb0.w), 0.f);
    v[4] = fmaxf(fmaf(di, acc[4], bb1.x), 0.f);
    v[5] = fmaxf(fmaf(di, acc[5], bb1.y), 0.f);
    v[6] = fmaxf(fmaf(di, acc[6], bb1.z), 0.f);
    v[7] = fmaxf(fmaf(di, acc[7], bb1.w), 0.f);

    // z = v @ W2
    float z0 = 0.f, z1 = 0.f;
#pragma unroll
    for (int k = 0; k < 4; k++) {
        float4 w = __ldg(&reinterpret_cast<const float4*>(W2)[4 * lane + k]);
        z0 = fmaf(v[2 * k], w.x, fmaf(v[2 * k + 1], w.z, z0));
        z1 = fmaf(v[2 * k], w.y, fmaf(v[2 * k + 1], w.w, z1));
    }
#pragma unroll
    for (int o = 16; o > 0; o >>= 1) {
        z0 += __shfl_xor_sync(0xffffffffu, z0, o);
        z1 += __shfl_xor_sync(0xffffffffu, z1, o);
    }
    if (lane == 0) {
        g_z[node * 2 + 0] = z0;
        g_z[node * 2 + 1] = z1;
        float s = di * di;
        out[node * 2 + 0] = fmaf(s, z0, __ldg(&b2[0]));
        out[node * 2 + 1] = fmaf(s, z1, __ldg(&b2[1]));
    }
}

// ---------------- final edge scatter of 2 features -----------------------------
__global__ void k_edge_agg_out(const int* __restrict__ ei, float* __restrict__ out) {
    int e = blockIdx.x * blockDim.x + threadIdx.x;
    if (e >= EE) return;
    int sh = g_shift;
    int s = edge_src(ei, e, sh);
    int d = edge_dst(ei, e, sh);
    float nrm = g_deg[s] * g_deg[d];
    float2 v = reinterpret_cast<const float2*>(g_z)[s];
    red_add_v2(out + (size_t)d * 2, v.x * nrm, v.y * nrm);
}

// ---------------- launch -----------------------------------------------------
extern "C" void kernel_launch(void* const* d_in, const int* in_sizes, int n_in,
                              void* d_out, int out_size) {
    const float* x = nullptr;
    const float* W1 = nullptr;
    const float* b1 = nullptr;
    const float* W2 = nullptr;
    const float* b2 = nullptr;
    const int* ei = nullptr;
    for (int i = 0; i < n_in; i++) {
        switch (in_sizes[i]) {
            case NN * IN_DIM:      x  = (const float*)d_in[i]; break;
            case IN_DIM * HID:     W1 = (const float*)d_in[i]; break;
            case HID:              b1 = (const float*)d_in[i]; break;
            case HID * OUTD:       W2 = (const float*)d_in[i]; break;
            case OUTD:             b2 = (const float*)d_in[i]; break;
            case 2 * EE:           ei = (const int*)d_in[i]; break;
            default: break;
        }
    }
    float* out = (float*)d_out;
    __half* d_h; cudaGetSymbolAddress((void**)&d_h, g_h);

    // side stream + events + func attr (host-side setup, done once)
    static cudaStream_t s2 = nullptr;
    static cudaEvent_t evFork = nullptr, evJoin = nullptr;
    if (!s2) {
        cudaStreamCreateWithFlags(&s2, cudaStreamNonBlocking);
        cudaEventCreateWithFlags(&evFork, cudaEventDisableTiming);
        cudaEventCreateWithFlags(&evJoin, cudaEventDisableTiming);
        cudaFuncSetAttribute(k_mma_gemm,
                             cudaFuncAttributeMaxDynamicSharedMemorySize, SMEM_BYTES);
    }

    const int T = 256;

    // edge dtype detection (needed by both branches)
    k_detect<<<1, 32>>>(ei);

    // fork: CSR build on s2, GEMM on main stream
    cudaEventRecord(evFork, 0);
    cudaStreamWaitEvent(s2, evFork, 0);

    k_zero_cnt<<<(NN + T - 1) / T, T, 0, s2>>>();
    k_deg_acc<<<(EE + T - 1) / T, T, 0, s2>>>(ei);
    k_dinv<<<(NN + T - 1) / T, T, 0, s2>>>();
    k_scan<<<1, 1024, 0, s2>>>();
    k_scatter<<<(EE + T - 1) / T, T, 0, s2>>>(ei);
    cudaEventRecord(evJoin, s2);

    // GEMM1 (tf32 tensor cores + cp.async): h = x @ W1 (fp16 output)
    {
        dim3 grid((NN + BM - 1) / BM, HID / BN);
        k_mma_gemm<<<grid, 256, SMEM_BYTES>>>(x, W1, d_h);
    }

    // join: aggregation needs CSR + dinv + h
    cudaStreamWaitEvent(0, evJoin, 0);

    {
        long long threads = (long long)NN * 32;
        k_agg_fused<<<(unsigned)((threads + T - 1) / T), T>>>(b1, W2, b2, out);
    }
    k_edge_agg_out<<<(EE + T - 1) / T, T>>>(ei, out);

    (void)out_size;
}

// round 7
// speedup vs baseline: 2.8297x; 1.0443x over previous
#include <cuda_runtime.h>
#include <cuda_fp16.h>
#include <cstdint>

#define NN 50000
#define EE 1600000
#define IN_DIM 1000
#define HID 256
#define OUTD 2

// ---------------- scratch (device globals; no allocation allowed) ----------
__device__ float  g_deg[NN];                // dinv (after k_dinv)
__device__ int    g_cnt[NN];                // in-degree histogram (no self-loop)
__device__ int    g_rowptr[NN + 1];         // CSR row pointers
__device__ int    g_wptr[NN];               // scatter cursors
__device__ int    g_csr_src[EE];            // CSR column (src) indices
__device__ __half g_h[(size_t)NN * HID];    // X @ W1  (fp16)
__device__ float  g_z[(size_t)NN * OUTD];   // relu(a+b1) @ W2
__device__ int    g_shift;                  // 0: edge_index int32, 1: int64

// ---------------- helpers ---------------------------------------------------
__device__ __forceinline__ void red_add_v2(float* p, float a, float b) {
    asm volatile("red.global.add.v2.f32 [%0], {%1,%2};"
                 :: "l"(p), "f"(a), "f"(b) : "memory");
}
__device__ __forceinline__ void cp_async16(void* smem_dst, const void* gsrc, bool valid) {
    uint32_t saddr = (uint32_t)__cvta_generic_to_shared(smem_dst);
    int sz = valid ? 16 : 0;   // src-size 0 -> 16B zero-fill
    asm volatile("cp.async.cg.shared.global [%0], [%1], 16, %2;"
                 :: "r"(saddr), "l"(gsrc), "r"(sz));
}
__device__ __forceinline__ void cp_async_commit() {
    asm volatile("cp.async.commit_group;");
}
// round-to-nearest fp32 -> tf32 on register (restores unbiased rounding)
__device__ __forceinline__ uint32_t rna(uint32_t raw) {
    uint32_t u;
    asm("cvt.rna.tf32.f32 %0, %1;" : "=r"(u) : "f"(__uint_as_float(raw)));
    return u;
}

// ---------------- edge dtype detection ---------------------------------------
__global__ void k_detect(const int* __restrict__ ei32) {
    int lane = threadIdx.x;
    unsigned any = 0;
    for (int base = 0; base < 2048; base += 32) {
        int v = ei32[2 * (base + lane) + 1];
        any |= __ballot_sync(0xffffffffu, v != 0);
    }
    if (lane == 0) g_shift = (any == 0) ? 1 : 0;
}
__device__ __forceinline__ int edge_src(const int* ei, int e, int sh) {
    return ei[(size_t)e << sh];
}
__device__ __forceinline__ int edge_dst(const int* ei, int e, int sh) {
    return ei[(size_t)(EE + e) << sh];
}

// ---------------- degree histogram / dinv -------------------------------------
__global__ void k_zero_cnt() {
    int i = blockIdx.x * blockDim.x + threadIdx.x;
    if (i < NN) g_cnt[i] = 0;
}
__global__ void k_deg_acc(const int* __restrict__ ei) {
    int e = blockIdx.x * blockDim.x + threadIdx.x;
    if (e < EE) {
        int sh = g_shift;
        atomicAdd(&g_cnt[edge_dst(ei, e, sh)], 1);
    }
}
__global__ void k_dinv() {
    int i = blockIdx.x * blockDim.x + threadIdx.x;
    if (i < NN) g_deg[i] = rsqrtf((float)(g_cnt[i] + 1));   // +1 self-loop
}

// ---------------- single-block exclusive scan (1024 threads, chunk=49) --------
__global__ void k_scan() {
    __shared__ int sums[1024];
    const int CH = 49;
    int t = threadIdx.x;
    int begN = t * CH;
    int endN = min(begN + CH, NN);
    int s = 0;
    for (int i = begN; i < endN; i++) s += g_cnt[i];
    sums[t] = s;
    __syncthreads();
    for (int off = 1; off < 1024; off <<= 1) {
        int v = (t >= off) ? sums[t - off] : 0;
        __syncthreads();
        sums[t] += v;
        __syncthreads();
    }
    int prefix = (t == 0) ? 0 : sums[t - 1];
    for (int i = begN; i < endN; i++) {
        g_rowptr[i] = prefix;
        g_wptr[i] = prefix;
        prefix += g_cnt[i];
    }
    if (t == 1023) g_rowptr[NN] = sums[1023];
}

// ---------------- CSR scatter --------------------------------------------------
__global__ void k_scatter(const int* __restrict__ ei) {
    int e = blockIdx.x * blockDim.x + threadIdx.x;
    if (e >= EE) return;
    int sh = g_shift;
    int s = edge_src(ei, e, sh);
    int d = edge_dst(ei, e, sh);
    int pos = atomicAdd(&g_wptr[d], 1);
    g_csr_src[pos] = s;
}

// ------ GEMM1: tf32 mma.sync (rna) + cp.async 3-stage, 128x256x16, 512 thr ----
#define BM 128
#define BN 256
#define BK 16
#define NIT ((IN_DIM + BK - 1) / BK)   // 63
#define AS_STRIDE 20                    // floats
#define BS_STRIDE 260                   // floats (256 + 4 pad)
#define STAGES 3
#define A_STAGE (BM * AS_STRIDE)
#define B_STAGE (BK * BS_STRIDE)
#define SMEM_BYTES ((STAGES * (A_STAGE + B_STAGE)) * 4)

__global__ __launch_bounds__(512, 1)
void k_mma_gemm(const float* __restrict__ A, const float* __restrict__ B,
                __half* __restrict__ Ch) {
    extern __shared__ float sm[];
    float* AsBase = sm;
    float* BsBase = sm + STAGES * A_STAGE;

    const int tid = threadIdx.x;
    const int bm = blockIdx.x * BM;

    const int warp = tid >> 5;
    const int lane = tid & 31;
    const int g = lane >> 2;
    const int t = lane & 3;
    const int warpM = warp >> 2;        // 0..3 -> 32 rows each
    const int warpN = warp & 3;         // 0..3 -> 64 cols each

    // staging coords: A tile = 512 float4 (one per thread); B tile = 1024 float4
    const int aRow = tid >> 2, aQ = tid & 3;
    const int bK0 = tid >> 6,          bQ0 = tid & 63;
    const int bK1 = (tid + 512) >> 6,  bQ1 = (tid + 512) & 63;

    auto issueStage = [&](int it) {
        int buf = it % STAGES;
        int k0 = it * BK;
        float* as = AsBase + buf * A_STAGE;
        float* bs = BsBase + buf * B_STAGE;
        int gr = bm + aRow;
        int ka = k0 + 4 * aQ;
        cp_async16(as + aRow * AS_STRIDE + 4 * aQ,
                   A + (size_t)gr * IN_DIM + ka, gr < NN && ka + 3 < IN_DIM);
        int kb0 = k0 + bK0, kb1 = k0 + bK1;
        cp_async16(bs + bK0 * BS_STRIDE + 4 * bQ0,
                   B + (size_t)kb0 * HID + 4 * bQ0, kb0 < IN_DIM);
        cp_async16(bs + bK1 * BS_STRIDE + 4 * bQ1,
                   B + (size_t)kb1 * HID + 4 * bQ1, kb1 < IN_DIM);
        cp_async_commit();
    };

    float acc[2][8][4];
#pragma unroll
    for (int mi = 0; mi < 2; mi++)
#pragma unroll
        for (int ni = 0; ni < 8; ni++)
#pragma unroll
            for (int c = 0; c < 4; c++) acc[mi][ni][c] = 0.f;

    issueStage(0);
    issueStage(1);

    for (int it = 0; it < NIT; ++it) {
        asm volatile("cp.async.wait_group 1;");
        __syncthreads();
        if (it + 2 < NIT) issueStage(it + 2);

        const int buf = it % STAGES;
        const uint32_t* as = reinterpret_cast<const uint32_t*>(AsBase + buf * A_STAGE);
        const uint32_t* bs = reinterpret_cast<const uint32_t*>(BsBase + buf * B_STAGE);
#pragma unroll
        for (int k8 = 0; k8 < 2; k8++) {
            const int kk = k8 * 8;
            uint32_t afr[2][4];
#pragma unroll
            for (int mi = 0; mi < 2; mi++) {
                const int rb = warpM * 32 + mi * 16;
                afr[mi][0] = rna(as[(rb + g    ) * AS_STRIDE + kk + t    ]);
                afr[mi][1] = rna(as[(rb + g + 8) * AS_STRIDE + kk + t    ]);
                afr[mi][2] = rna(as[(rb + g    ) * AS_STRIDE + kk + t + 4]);
                afr[mi][3] = rna(as[(rb + g + 8) * AS_STRIDE + kk + t + 4]);
            }
#pragma unroll
            for (int ni = 0; ni < 8; ni++) {
                const int n = warpN * 64 + ni * 8 + g;
                uint32_t b0 = rna(bs[(kk + t    ) * BS_STRIDE + n]);
                uint32_t b1 = rna(bs[(kk + t + 4) * BS_STRIDE + n]);
#pragma unroll
                for (int mi = 0; mi < 2; mi++) {
                    asm volatile(
                        "mma.sync.aligned.m16n8k8.row.col.f32.tf32.tf32.f32 "
                        "{%0,%1,%2,%3}, {%4,%5,%6,%7}, {%8,%9}, {%0,%1,%2,%3};"
                        : "+f"(acc[mi][ni][0]), "+f"(acc[mi][ni][1]),
                          "+f"(acc[mi][ni][2]), "+f"(acc[mi][ni][3])
                        : "r"(afr[mi][0]), "r"(afr[mi][1]),
                          "r"(afr[mi][2]), "r"(afr[mi][3]),
                          "r"(b0), "r"(b1));
                }
            }
        }
    }

    // epilogue: h (fp16)
#pragma unroll
    for (int mi = 0; mi < 2; mi++) {
#pragma unroll
        for (int half = 0; half < 2; half++) {
            int r = bm + warpM * 32 + mi * 16 + g + half * 8;
            if (r >= NN) continue;
            size_t rowOff = (size_t)r * HID + warpN * 64 + 2 * t;
#pragma unroll
            for (int ni = 0; ni < 8; ni++) {
                __half2 hv = __floats2half2_rn(acc[mi][ni][half * 2 + 0],
                                               acc[mi][ni][half * 2 + 1]);
                *reinterpret_cast<__half2*>(Ch + rowOff + ni * 8) = hv;
            }
        }
    }
}

// ---------------- fused: CSR aggregate + bias + relu + W2 + out init ----------
__global__ __launch_bounds__(256)
void k_agg_fused(const float* __restrict__ b1, const float* __restrict__ W2,
                 const float* __restrict__ b2, float* __restrict__ out) {
    int node = (blockIdx.x * blockDim.x + threadIdx.x) >> 5;
    int lane = threadIdx.x & 31;
    if (node >= NN) return;

    int beg = g_rowptr[node];
    int end = g_rowptr[node + 1];
    float di = g_deg[node];

    float acc[8];
#pragma unroll
    for (int c = 0; c < 8; c++) acc[c] = 0.f;

    auto accumU = [&](uint4 u, float w) {
        float2 f0 = __half22float2(*reinterpret_cast<__half2*>(&u.x));
        float2 f1 = __half22float2(*reinterpret_cast<__half2*>(&u.y));
        float2 f2 = __half22float2(*reinterpret_cast<__half2*>(&u.z));
        float2 f3 = __half22float2(*reinterpret_cast<__half2*>(&u.w));
        acc[0] = fmaf(w, f0.x, acc[0]); acc[1] = fmaf(w, f0.y, acc[1]);
        acc[2] = fmaf(w, f1.x, acc[2]); acc[3] = fmaf(w, f1.y, acc[3]);
        acc[4] = fmaf(w, f2.x, acc[4]); acc[5] = fmaf(w, f2.y, acc[5]);
        acc[6] = fmaf(w, f3.x, acc[6]); acc[7] = fmaf(w, f3.y, acc[7]);
    };

    for (int base = beg; base < end; base += 32) {
        int e = base + lane;
        int s = -1;
        float ds = 0.f;
        if (e < end) {
            s = __ldg(&g_csr_src[e]);
            ds = __ldg(&g_deg[s]);
        }
        int cnt = min(32, end - base);
        int j = 0;
        for (; j + 4 <= cnt; j += 4) {
            int s0 = __shfl_sync(0xffffffffu, s, j);
            int s1 = __shfl_sync(0xffffffffu, s, j + 1);
            int s2 = __shfl_sync(0xffffffffu, s, j + 2);
            int s3 = __shfl_sync(0xffffffffu, s, j + 3);
            float w0 = __shfl_sync(0xffffffffu, ds, j);
            float w1 = __shfl_sync(0xffffffffu, ds, j + 1);
            float w2 = __shfl_sync(0xffffffffu, ds, j + 2);
            float w3 = __shfl_sync(0xffffffffu, ds, j + 3);
            uint4 u0 = __ldg(&reinterpret_cast<const uint4*>(g_h + (size_t)s0 * HID)[lane]);
            uint4 u1 = __ldg(&reinterpret_cast<const uint4*>(g_h + (size_t)s1 * HID)[lane]);
            uint4 u2 = __ldg(&reinterpret_cast<const uint4*>(g_h + (size_t)s2 * HID)[lane]);
            uint4 u3 = __ldg(&reinterpret_cast<const uint4*>(g_h + (size_t)s3 * HID)[lane]);
            accumU(u0, w0); accumU(u1, w1); accumU(u2, w2); accumU(u3, w3);
        }
        for (; j < cnt; j++) {
            int sj = __shfl_sync(0xffffffffu, s, j);
            float w = __shfl_sync(0xffffffffu, ds, j);
            uint4 u = __ldg(&reinterpret_cast<const uint4*>(g_h + (size_t)sj * HID)[lane]);
            accumU(u, w);
        }
    }
    {   // self-loop
        uint4 u = __ldg(&reinterpret_cast<const uint4*>(g_h + (size_t)node * HID)[lane]);
        accumU(u, di);
    }

    float4 bb0 = __ldg(&reinterpret_cast<const float4*>(b1)[2 * lane]);
    float4 bb1 = __ldg(&reinterpret_cast<const float4*>(b1)[2 * lane + 1]);
    float v[8];
    v[0] = fmaxf(fmaf(di, acc[0], bb0.x), 0.f);
    v[1] = fmaxf(fmaf(di, acc[1], bb0.y), 0.f);
    v[2] = fmaxf(fmaf(di, acc[2], bb0.z), 0.f);
    v[3] = fmaxf(fmaf(di, acc[3], bb0.w), 0.f);
    v[4] = fmaxf(fmaf(di, acc[4], bb1.x), 0.f);
    v[5] = fmaxf(fmaf(di, acc[5], bb1.y), 0.f);
    v[6] = fmaxf(fmaf(di, acc[6], bb1.z), 0.f);
    v[7] = fmaxf(fmaf(di, acc[7], bb1.w), 0.f);

    float z0 = 0.f, z1 = 0.f;
#pragma unroll
    for (int k = 0; k < 4; k++) {
        float4 w = __ldg(&reinterpret_cast<const float4*>(W2)[4 * lane + k]);
        z0 = fmaf(v[2 * k], w.x, fmaf(v[2 * k + 1], w.z, z0));
        z1 = fmaf(v[2 * k], w.y, fmaf(v[2 * k + 1], w.w, z1));
    }
#pragma unroll
    for (int o = 16; o > 0; o >>= 1) {
        z0 += __shfl_xor_sync(0xffffffffu, z0, o);
        z1 += __shfl_xor_sync(0xffffffffu, z1, o);
    }
    if (lane == 0) {
        g_z[node * 2 + 0] = z0;
        g_z[node * 2 + 1] = z1;
        float s = di * di;
        out[node * 2 + 0] = fmaf(s, z0, __ldg(&b2[0]));
        out[node * 2 + 1] = fmaf(s, z1, __ldg(&b2[1]));
    }
}

// ---------------- final edge scatter of 2 features -----------------------------
__global__ void k_edge_agg_out(const int* __restrict__ ei, float* __restrict__ out) {
    int e = blockIdx.x * blockDim.x + threadIdx.x;
    if (e >= EE) return;
    int sh = g_shift;
    int s = edge_src(ei, e, sh);
    int d = edge_dst(ei, e, sh);
    float nrm = g_deg[s] * g_deg[d];
    float2 v = reinterpret_cast<const float2*>(g_z)[s];
    red_add_v2(out + (size_t)d * 2, v.x * nrm, v.y * nrm);
}

// ---------------- launch -----------------------------------------------------
extern "C" void kernel_launch(void* const* d_in, const int* in_sizes, int n_in,
                              void* d_out, int out_size) {
    const float* x = nullptr;
    const float* W1 = nullptr;
    const float* b1 = nullptr;
    const float* W2 = nullptr;
    const float* b2 = nullptr;
    const int* ei = nullptr;
    for (int i = 0; i < n_in; i++) {
        switch (in_sizes[i]) {
            case NN * IN_DIM:      x  = (const float*)d_in[i]; break;
            case IN_DIM * HID:     W1 = (const float*)d_in[i]; break;
            case HID:              b1 = (const float*)d_in[i]; break;
            case HID * OUTD:       W2 = (const float*)d_in[i]; break;
            case OUTD:             b2 = (const float*)d_in[i]; break;
            case 2 * EE:           ei = (const int*)d_in[i]; break;
            default: break;
        }
    }
    float* out = (float*)d_out;
    __half* d_h; cudaGetSymbolAddress((void**)&d_h, g_h);

    static cudaStream_t s2 = nullptr;
    static cudaEvent_t evFork = nullptr, evJoin = nullptr;
    if (!s2) {
        cudaStreamCreateWithFlags(&s2, cudaStreamNonBlocking);
        cudaEventCreateWithFlags(&evFork, cudaEventDisableTiming);
        cudaEventCreateWithFlags(&evJoin, cudaEventDisableTiming);
        cudaFuncSetAttribute(k_mma_gemm,
                             cudaFuncAttributeMaxDynamicSharedMemorySize, SMEM_BYTES);
    }

    const int T = 256;

    // launch #1
    k_detect<<<1, 32>>>(ei);

    cudaEventRecord(evFork, 0);
    cudaStreamWaitEvent(s2, evFork, 0);

    // launches #2..#5 (CSR chain prefix on s2)
    k_zero_cnt<<<(NN + T - 1) / T, T, 0, s2>>>();
    k_deg_acc<<<(EE + T - 1) / T, T, 0, s2>>>(ei);
    k_dinv<<<(NN + T - 1) / T, T, 0, s2>>>();
    k_scan<<<1, 1024, 0, s2>>>();

    // launch #6 = GEMM (ncu -s 5 -c 1 captures this one)
    {
        dim3 grid((NN + BM - 1) / BM, 1);
        k_mma_gemm<<<grid, 512, SMEM_BYTES>>>(x, W1, d_h);
    }

    // launch #7 (rest of CSR chain on s2)
    k_scatter<<<(EE + T - 1) / T, T, 0, s2>>>(ei);
    cudaEventRecord(evJoin, s2);

    // join: aggregation needs CSR + dinv + h
    cudaStreamWaitEvent(0, evJoin, 0);

    {
        long long threads = (long long)NN * 32;
        k_agg_fused<<<(unsigned)((threads + T - 1) / T), T>>>(b1, W2, b2, out);
    }
    k_edge_agg_out<<<(EE + T - 1) / T, T>>>(ei, out);

    (void)out_size;
}

// round 8
// speedup vs baseline: 3.2405x; 1.1452x over previous
#include <cuda_runtime.h>
#include <cuda_fp16.h>
#include <cstdint>

#define NN 50000
#define EE 1600000
#define IN_DIM 1000
#define HID 256
#define OUTD 2

// ---------------- scratch (device globals; no allocation allowed) ----------
__device__ float  g_deg[NN];                // dinv (after k_dinv)
__device__ int    g_cnt[NN];                // in-degree histogram (no self-loop)
__device__ int    g_rowptr[NN + 1];         // CSR row pointers
__device__ int    g_wptr[NN];               // scatter cursors
__device__ int    g_csr_src[EE];            // CSR column (src) indices
__device__ __half g_h[(size_t)NN * HID];    // X @ W1  (fp16)
__device__ __half g_w1i[(IN_DIM / 2) * HID * 2];  // W1 fp16, [k/2][n][2] interleave
__device__ float  g_z[(size_t)NN * OUTD];   // relu(a+b1) @ W2
__device__ int    g_shift;                  // 0: edge_index int32, 1: int64

// ---------------- helpers ---------------------------------------------------
__device__ __forceinline__ void red_add_v2(float* p, float a, float b) {
    asm volatile("red.global.add.v2.f32 [%0], {%1,%2};"
                 :: "l"(p), "f"(a), "f"(b) : "memory");
}
__device__ __forceinline__ void cp_async16(void* smem_dst, const void* gsrc, bool valid) {
    uint32_t saddr = (uint32_t)__cvta_generic_to_shared(smem_dst);
    int sz = valid ? 16 : 0;   // src-size 0 -> 16B zero-fill
    asm volatile("cp.async.cg.shared.global [%0], [%1], 16, %2;"
                 :: "r"(saddr), "l"(gsrc), "r"(sz));
}
__device__ __forceinline__ void cp_async_commit() {
    asm volatile("cp.async.commit_group;");
}
// pack two fp32 -> half2 {lo, hi} with round-to-nearest
__device__ __forceinline__ uint32_t pack_h2(float lo, float hi) {
    uint32_t d;
    asm("cvt.rn.f16x2.f32 %0, %1, %2;" : "=r"(d) : "f"(hi), "f"(lo));
    return d;
}

// ---------------- edge dtype detection ---------------------------------------
__global__ void k_detect(const int* __restrict__ ei32) {
    int lane = threadIdx.x;
    unsigned any = 0;
    for (int base = 0; base < 2048; base += 32) {
        int v = ei32[2 * (base + lane) + 1];
        any |= __ballot_sync(0xffffffffu, v != 0);
    }
    if (lane == 0) g_shift = (any == 0) ? 1 : 0;
}
__device__ __forceinline__ int edge_src(const int* ei, int e, int sh) {
    return ei[(size_t)e << sh];
}
__device__ __forceinline__ int edge_dst(const int* ei, int e, int sh) {
    return ei[(size_t)(EE + e) << sh];
}

// ---------------- W1 -> fp16 interleaved [k/2][n][2] ---------------------------
__global__ void k_cvt_w1(const float* __restrict__ W1) {
    int idx = blockIdx.x * blockDim.x + threadIdx.x;   // over (IN_DIM/2)*HID
    if (idx >= (IN_DIM / 2) * HID) return;
    int p = idx / HID, n = idx % HID;
    g_w1i[p * (2 * HID) + 2 * n + 0] = __float2half_rn(W1[(2 * p) * HID + n]);
    g_w1i[p * (2 * HID) + 2 * n + 1] = __float2half_rn(W1[(2 * p + 1) * HID + n]);
}

// ---------------- degree histogram / dinv -------------------------------------
__global__ void k_zero_cnt() {
    int i = blockIdx.x * blockDim.x + threadIdx.x;
    if (i < NN) g_cnt[i] = 0;
}
__global__ void k_deg_acc(const int* __restrict__ ei) {
    int e = blockIdx.x * blockDim.x + threadIdx.x;
    if (e < EE) {
        int sh = g_shift;
        atomicAdd(&g_cnt[edge_dst(ei, e, sh)], 1);
    }
}
__global__ void k_dinv() {
    int i = blockIdx.x * blockDim.x + threadIdx.x;
    if (i < NN) g_deg[i] = rsqrtf((float)(g_cnt[i] + 1));   // +1 self-loop
}

// ---------------- single-block exclusive scan (1024 threads, chunk=49) --------
__global__ void k_scan() {
    __shared__ int sums[1024];
    const int CH = 49;
    int t = threadIdx.x;
    int begN = t * CH;
    int endN = min(begN + CH, NN);
    int s = 0;
    for (int i = begN; i < endN; i++) s += g_cnt[i];
    sums[t] = s;
    __syncthreads();
    for (int off = 1; off < 1024; off <<= 1) {
        int v = (t >= off) ? sums[t - off] : 0;
        __syncthreads();
        sums[t] += v;
        __syncthreads();
    }
    int prefix = (t == 0) ? 0 : sums[t - 1];
    for (int i = begN; i < endN; i++) {
        g_rowptr[i] = prefix;
        g_wptr[i] = prefix;
        prefix += g_cnt[i];
    }
    if (t == 1023) g_rowptr[NN] = sums[1023];
}

// ---------------- CSR scatter --------------------------------------------------
__global__ void k_scatter(const int* __restrict__ ei) {
    int e = blockIdx.x * blockDim.x + threadIdx.x;
    if (e >= EE) return;
    int sh = g_shift;
    int s = edge_src(ei, e, sh);
    int d = edge_dst(ei, e, sh);
    int pos = atomicAdd(&g_wptr[d], 1);
    g_csr_src[pos] = s;
}

// ------ GEMM1: fp16 mma.sync m16n8k16 + cp.async 4-stage, 128x256x16, 512 thr -
#define BM 128
#define BN 256
#define BK 16
#define NIT ((IN_DIM + BK - 1) / BK)     // 63
#define AS_STRIDE 20                      // floats per A row (16 + 4 pad)
#define STAGES 4
#define A_STAGE_F (BM * AS_STRIDE)        // floats per A stage (10240 B)
#define B_PAIRS (BK / 2)                  // 8 k-pairs per stage
#define B_ROW_BYTES 1040                  // 256 n * 2 halfs * 2B + 16B pad
#define B_ROW_WORDS (B_ROW_BYTES / 4)     // 260
#define B_STAGE_BYTES (B_PAIRS * B_ROW_BYTES)   // 8320
#define A_BYTES (STAGES * A_STAGE_F * 4)
#define SMEM_BYTES (A_BYTES + STAGES * B_STAGE_BYTES)

__global__ __launch_bounds__(512, 1)
void k_mma_gemm(const float* __restrict__ A, __half* __restrict__ Ch) {
    extern __shared__ char smraw[];
    float* AsBase = reinterpret_cast<float*>(smraw);
    char*  BsBase = smraw + A_BYTES;

    const int tid = threadIdx.x;
    const int bm = blockIdx.x * BM;

    const int warp = tid >> 5;
    const int lane = tid & 31;
    const int g = lane >> 2;
    const int t = lane & 3;
    const int warpM = warp >> 2;        // 0..3 -> 32 rows each
    const int warpN = warp & 3;         // 0..3 -> 64 cols each

    // staging coords
    const int aRow = tid >> 2, aQ = tid & 3;        // A: 512 chunks, 1/thread
    const int bPair = tid >> 6, bChunk = tid & 63;  // B: 512 chunks, 1/thread

    auto issueStage = [&](int it) {
        int buf = it % STAGES;
        int k0 = it * BK;
        float* as = AsBase + buf * A_STAGE_F;
        char*  bs = BsBase + buf * B_STAGE_BYTES;
        int gr = bm + aRow;
        int ka = k0 + 4 * aQ;
        cp_async16(as + aRow * AS_STRIDE + 4 * aQ,
                   A + (size_t)gr * IN_DIM + ka, gr < NN && ka + 3 < IN_DIM);
        int gp = (k0 >> 1) + bPair;     // global k-pair
        cp_async16(bs + bPair * B_ROW_BYTES + bChunk * 16,
                   g_w1i + (size_t)gp * (2 * HID) + bChunk * 8, gp < IN_DIM / 2);
        cp_async_commit();
    };

    float acc[2][8][4];
#pragma unroll
    for (int mi = 0; mi < 2; mi++)
#pragma unroll
        for (int ni = 0; ni < 8; ni++)
#pragma unroll
            for (int c = 0; c < 4; c++) acc[mi][ni][c] = 0.f;

    issueStage(0);
    issueStage(1);
    issueStage(2);

    for (int it = 0; it < NIT; ++it) {
        asm volatile("cp.async.wait_group 2;");
        __syncthreads();
        if (it + 3 < NIT) issueStage(it + 3);

        const int buf = it % STAGES;
        const float* as = AsBase + buf * A_STAGE_F;
        const uint32_t* bw = reinterpret_cast<const uint32_t*>(BsBase + buf * B_STAGE_BYTES);

        // A fragments (fp32 smem -> half2 regs)
        uint32_t afr[2][4];
#pragma unroll
        for (int mi = 0; mi < 2; mi++) {
            const int rb = warpM * 32 + mi * 16;
            const float* r0 = as + (rb + g) * AS_STRIDE + 2 * t;
            const float* r1 = as + (rb + g + 8) * AS_STRIDE + 2 * t;
            float2 fa = *reinterpret_cast<const float2*>(r0);
            float2 fb = *reinterpret_cast<const float2*>(r1);
            float2 fc = *reinterpret_cast<const float2*>(r0 + 8);
            float2 fd = *reinterpret_cast<const float2*>(r1 + 8);
            afr[mi][0] = pack_h2(fa.x, fa.y);
            afr[mi][1] = pack_h2(fb.x, fb.y);
            afr[mi][2] = pack_h2(fc.x, fc.y);
            afr[mi][3] = pack_h2(fd.x, fd.y);
        }
#pragma unroll
        for (int ni = 0; ni < 8; ni++) {
            const int n = warpN * 64 + ni * 8 + g;
            uint32_t b0 = bw[t * B_ROW_WORDS + n];          // k rows 2t,2t+1
            uint32_t b1 = bw[(t + 4) * B_ROW_WORDS + n];    // k rows 8+2t,8+2t+1
#pragma unroll
            for (int mi = 0; mi < 2; mi++) {
                asm volatile(
                    "mma.sync.aligned.m16n8k16.row.col.f32.f16.f16.f32 "
                    "{%0,%1,%2,%3}, {%4,%5,%6,%7}, {%8,%9}, {%0,%1,%2,%3};"
                    : "+f"(acc[mi][ni][0]), "+f"(acc[mi][ni][1]),
                      "+f"(acc[mi][ni][2]), "+f"(acc[mi][ni][3])
                    : "r"(afr[mi][0]), "r"(afr[mi][1]),
                      "r"(afr[mi][2]), "r"(afr[mi][3]),
                      "r"(b0), "r"(b1));
            }
        }
    }

    // epilogue: h (fp16)
#pragma unroll
    for (int mi = 0; mi < 2; mi++) {
#pragma unroll
        for (int half = 0; half < 2; half++) {
            int r = bm + warpM * 32 + mi * 16 + g + half * 8;
            if (r >= NN) continue;
            size_t rowOff = (size_t)r * HID + warpN * 64 + 2 * t;
#pragma unroll
            for (int ni = 0; ni < 8; ni++) {
                __half2 hv = __floats2half2_rn(acc[mi][ni][half * 2 + 0],
                                               acc[mi][ni][half * 2 + 1]);
                *reinterpret_cast<__half2*>(Ch + rowOff + ni * 8) = hv;
            }
        }
    }
}

// ---------------- fused: CSR aggregate + bias + relu + W2 + out init ----------
__global__ __launch_bounds__(256)
void k_agg_fused(const float* __restrict__ b1, const float* __restrict__ W2,
                 const float* __restrict__ b2, float* __restrict__ out) {
    int node = (blockIdx.x * blockDim.x + threadIdx.x) >> 5;
    int lane = threadIdx.x & 31;
    if (node >= NN) return;

    int beg = g_rowptr[node];
    int end = g_rowptr[node + 1];
    float di = g_deg[node];

    float acc[8];
#pragma unroll
    for (int c = 0; c < 8; c++) acc[c] = 0.f;

    auto accumU = [&](uint4 u, float w) {
        float2 f0 = __half22float2(*reinterpret_cast<__half2*>(&u.x));
        float2 f1 = __half22float2(*reinterpret_cast<__half2*>(&u.y));
        float2 f2 = __half22float2(*reinterpret_cast<__half2*>(&u.z));
        float2 f3 = __half22float2(*reinterpret_cast<__half2*>(&u.w));
        acc[0] = fmaf(w, f0.x, acc[0]); acc[1] = fmaf(w, f0.y, acc[1]);
        acc[2] = fmaf(w, f1.x, acc[2]); acc[3] = fmaf(w, f1.y, acc[3]);
        acc[4] = fmaf(w, f2.x, acc[4]); acc[5] = fmaf(w, f2.y, acc[5]);
        acc[6] = fmaf(w, f3.x, acc[6]); acc[7] = fmaf(w, f3.y, acc[7]);
    };

    for (int base = beg; base < end; base += 32) {
        int e = base + lane;
        int s = -1;
        float ds = 0.f;
        if (e < end) {
            s = __ldg(&g_csr_src[e]);
            ds = __ldg(&g_deg[s]);
        }
        int cnt = min(32, end - base);
        int j = 0;
        for (; j + 4 <= cnt; j += 4) {
            int s0 = __shfl_sync(0xffffffffu, s, j);
            int s1 = __shfl_sync(0xffffffffu, s, j + 1);
            int s2 = __shfl_sync(0xffffffffu, s, j + 2);
            int s3 = __shfl_sync(0xffffffffu, s, j + 3);
            float w0 = __shfl_sync(0xffffffffu, ds, j);
            float w1 = __shfl_sync(0xffffffffu, ds, j + 1);
            float w2 = __shfl_sync(0xffffffffu, ds, j + 2);
            float w3 = __shfl_sync(0xffffffffu, ds, j + 3);
            uint4 u0 = __ldg(&reinterpret_cast<const uint4*>(g_h + (size_t)s0 * HID)[lane]);
            uint4 u1 = __ldg(&reinterpret_cast<const uint4*>(g_h + (size_t)s1 * HID)[lane]);
            uint4 u2 = __ldg(&reinterpret_cast<const uint4*>(g_h + (size_t)s2 * HID)[lane]);
            uint4 u3 = __ldg(&reinterpret_cast<const uint4*>(g_h + (size_t)s3 * HID)[lane]);
            accumU(u0, w0); accumU(u1, w1); accumU(u2, w2); accumU(u3, w3);
        }
        for (; j < cnt; j++) {
            int sj = __shfl_sync(0xffffffffu, s, j);
            float w = __shfl_sync(0xffffffffu, ds, j);
            uint4 u = __ldg(&reinterpret_cast<const uint4*>(g_h + (size_t)sj * HID)[lane]);
            accumU(u, w);
        }
    }
    {   // self-loop
        uint4 u = __ldg(&reinterpret_cast<const uint4*>(g_h + (size_t)node * HID)[lane]);
        accumU(u, di);
    }

    float4 bb0 = __ldg(&reinterpret_cast<const float4*>(b1)[2 * lane]);
    float4 bb1 = __ldg(&reinterpret_cast<const float4*>(b1)[2 * lane + 1]);
    float v[8];
    v[0] = fmaxf(fmaf(di, acc[0], bb0.x), 0.f);
    v[1] = fmaxf(fmaf(di, acc[1], bb0.y), 0.f);
    v[2] = fmaxf(fmaf(di, acc[2], bb0.z), 0.f);
    v[3] = fmaxf(fmaf(di, acc[3], bb0.w), 0.f);
    v[4] = fmaxf(fmaf(di, acc[4], bb1.x), 0.f);
    v[5] = fmaxf(fmaf(di, acc[5], bb1.y), 0.f);
    v[6] = fmaxf(fmaf(di, acc[6], bb1.z), 0.f);
    v[7] = fmaxf(fmaf(di, acc[7], bb1.w), 0.f);

    float z0 = 0.f, z1 = 0.f;
#pragma unroll
    for (int k = 0; k < 4; k++) {
        float4 w = __ldg(&reinterpret_cast<const float4*>(W2)[4 * lane + k]);
        z0 = fmaf(v[2 * k], w.x, fmaf(v[2 * k + 1], w.z, z0));
        z1 = fmaf(v[2 * k], w.y, fmaf(v[2 * k + 1], w.w, z1));
    }
#pragma unroll
    for (int o = 16; o > 0; o >>= 1) {
        z0 += __shfl_xor_sync(0xffffffffu, z0, o);
        z1 += __shfl_xor_sync(0xffffffffu, z1, o);
    }
    if (lane == 0) {
        g_z[node * 2 + 0] = z0;
        g_z[node * 2 + 1] = z1;
        float s = di * di;
        out[node * 2 + 0] = fmaf(s, z0, __ldg(&b2[0]));
        out[node * 2 + 1] = fmaf(s, z1, __ldg(&b2[1]));
    }
}

// ---------------- final edge scatter of 2 features -----------------------------
__global__ void k_edge_agg_out(const int* __restrict__ ei, float* __restrict__ out) {
    int e = blockIdx.x * blockDim.x + threadIdx.x;
    if (e >= EE) return;
    int sh = g_shift;
    int s = edge_src(ei, e, sh);
    int d = edge_dst(ei, e, sh);
    float nrm = g_deg[s] * g_deg[d];
    float2 v = reinterpret_cast<const float2*>(g_z)[s];
    red_add_v2(out + (size_t)d * 2, v.x * nrm, v.y * nrm);
}

// ---------------- launch -----------------------------------------------------
extern "C" void kernel_launch(void* const* d_in, const int* in_sizes, int n_in,
                              void* d_out, int out_size) {
    const float* x = nullptr;
    const float* W1 = nullptr;
    const float* b1 = nullptr;
    const float* W2 = nullptr;
    const float* b2 = nullptr;
    const int* ei = nullptr;
    for (int i = 0; i < n_in; i++) {
        switch (in_sizes[i]) {
            case NN * IN_DIM:      x  = (const float*)d_in[i]; break;
            case IN_DIM * HID:     W1 = (const float*)d_in[i]; break;
            case HID:              b1 = (const float*)d_in[i]; break;
            case HID * OUTD:       W2 = (const float*)d_in[i]; break;
            case OUTD:             b2 = (const float*)d_in[i]; break;
            case 2 * EE:           ei = (const int*)d_in[i]; break;
            default: break;
        }
    }
    float* out = (float*)d_out;
    __half* d_h; cudaGetSymbolAddress((void**)&d_h, g_h);

    static cudaStream_t s2 = nullptr;
    static cudaEvent_t evFork = nullptr, evJoin = nullptr;
    if (!s2) {
        cudaStreamCreateWithFlags(&s2, cudaStreamNonBlocking);
        cudaEventCreateWithFlags(&evFork, cudaEventDisableTiming);
        cudaEventCreateWithFlags(&evJoin, cudaEventDisableTiming);
        cudaFuncSetAttribute(k_mma_gemm,
                             cudaFuncAttributeMaxDynamicSharedMemorySize, SMEM_BYTES);
    }

    const int T = 256;

    // main stream: W1 conversion (GEMM depends on it, same stream)
    k_cvt_w1<<<((IN_DIM / 2) * HID + T - 1) / T, T>>>(W1);
    k_detect<<<1, 32>>>(ei);

    // fork: CSR build on s2
    cudaEventRecord(evFork, 0);
    cudaStreamWaitEvent(s2, evFork, 0);
    k_zero_cnt<<<(NN + T - 1) / T, T, 0, s2>>>();
    k_deg_acc<<<(EE + T - 1) / T, T, 0, s2>>>(ei);
    k_dinv<<<(NN + T - 1) / T, T, 0, s2>>>();
    k_scan<<<1, 1024, 0, s2>>>();
    k_scatter<<<(EE + T - 1) / T, T, 0, s2>>>(ei);
    cudaEventRecord(evJoin, s2);

    // GEMM1 (fp16 mma m16n8k16): h = x @ W1 (fp16 output)
    {
        dim3 grid((NN + BM - 1) / BM, 1);
        k_mma_gemm<<<grid, 512, SMEM_BYTES>>>(x, d_h);
    }

    // join: aggregation needs CSR + dinv + h
    cudaStreamWaitEvent(0, evJoin, 0);

    {
        long long threads = (long long)NN * 32;
        k_agg_fused<<<(unsigned)((threads + T - 1) / T), T>>>(b1, W2, b2, out);
    }
    k_edge_agg_out<<<(EE + T - 1) / T, T>>>(ei, out);

    (void)out_size;
}